// round 13
// baseline (speedup 1.0000x reference)
#include <cuda_runtime.h>
#include <math.h>
#include <stdint.h>

namespace {
constexpr int Tn  = 2048;
constexpr int Dn  = 512;
constexpr int NHn = 8;
constexpr int DHn = 64;
constexpr int CAPn = 512;
constexpr int NEn = 8;
}

// ---------------- scratch (static device globals; no runtime allocation) ----------------
__device__ float d_h[Tn * Dn];
__device__ float d_u[Tn * Dn];
__device__ float d_qkv[Tn * 3 * Dn];
__device__ float d_att[Tn * Dn];
__device__ float d_cos[Tn * DHn];
__device__ float d_sin[Tn * DHn];
__device__ float d_sc[(size_t)NHn * Tn * Tn];
__device__ float d_logits[Tn * 9];
__device__ float d_probs8[Tn * NEn];
__device__ float d_g[NEn * Tn];
__device__ int   d_cof[NEn * Tn];
__device__ int   d_slot[NEn * CAPn];
__device__ float d_xin[NEn * CAPn * Dn];
__device__ float d_eu[NEn * CAPn * Dn];          // [attn0..3 | ffn0..3] normalized inputs
__device__ float d_eqkv[4 * CAPn * 3 * Dn];
__device__ float d_eatt[4 * CAPn * Dn];
__device__ float d_ffh[4 * CAPn * 4 * Dn];
__device__ float d_exout[NEn * CAPn * Dn];

// ======================= TF32x3 tensor-core GEMM (fp32-accurate) =======================
// Two tile variants, numerically identical (same per-output K accumulation order):
//   gemm_tf32x3   : 128x64 CTA tile, 256 thr, 2 CTA/SM — best per-FLOP (large grids)
//   gemm64_tf32x3 :  64x64 CTA tile, 128 thr, 4 CTA/SM — 2x CTAs (small, starved grids)
// C[M,N] = act( alpha * A * op(B) ) (+R).  A: row-major MxK (lda).
// BNT=true : B row-major NxK (ldb)  -> C = A * B^T
// BNT=false: B row-major KxN (ldb)  -> C = A * B
// causal (NT): skip output tiles fully above the diagonal.
// causal (NN): clamp K to bm+tileM (A columns beyond hold exact zeros).
// zsplit: batch index decomposes as z = zhi*8 + zlo with strides (s?2, s?1).
__device__ __forceinline__ uint32_t f2tf32(float x) {
    uint32_t r; asm("cvt.rna.tf32.f32 %0, %1;" : "=r"(r) : "f"(x)); return r;
}
// hi: RNA-rounded tf32. lo: residual passed RAW — tensor core reads .tf32 operands
// as the top 19 bits (implicit RZ truncation); truncation error <= 2^-25 |v|.
__device__ __forceinline__ void split1(float v, uint32_t& hi, uint32_t& lo) {
    hi = f2tf32(v);
    lo = __float_as_uint(v - __uint_as_float(hi));
}
// cyclic rotate-left so that position j holds element (j+r)&3
__device__ __forceinline__ float4 rotl4(float4 t, int r) {
    if (r & 1) t = make_float4(t.y, t.z, t.w, t.x);
    if (r & 2) t = make_float4(t.z, t.w, t.x, t.y);
    return t;
}
__device__ __forceinline__ int4 rotl4(int4 t, int r) {
    if (r & 1) t = make_int4(t.y, t.z, t.w, t.x);
    if (r & 2) t = make_int4(t.z, t.w, t.x, t.y);
    return t;
}

#define MMA_TF32(c0,c1,c2,c3,a0,a1,a2,a3,b0,b1)                                  \
    asm volatile("mma.sync.aligned.m16n8k8.row.col.f32.tf32.tf32.f32 "           \
                 "{%0,%1,%2,%3}, {%4,%5,%6,%7}, {%8,%9}, {%0,%1,%2,%3};"         \
                 : "+f"(c0), "+f"(c1), "+f"(c2), "+f"(c3)                         \
                 : "r"(a0), "r"(a1), "r"(a2), "r"(a3), "r"(b0), "r"(b1))

template<bool BNT>
__global__ void __launch_bounds__(256, 2)
gemm_tf32x3(const float* __restrict__ A, const float* __restrict__ B,
            float* __restrict__ C, const float* __restrict__ R,
            int M, int N, int K, int lda, int ldb, int ldc, int ldr,
            long long sA, long long sB, long long sC, long long sR,
            float alpha, int act, int causal,
            int zsplit, long long sA2, long long sB2, long long sC2)
{
    __shared__ float4 As[2][1024];
    __shared__ float2 Bs[2][1024];
    float* asw = (float*)As;
    float* bsw = (float*)Bs;

    int z = blockIdx.z;
    if (zsplit) {
        int zh = z >> 3, zl = z & 7;
        A += zh * sA2 + zl * sA;
        B += zh * sB2 + zl * sB;
        C += zh * sC2 + zl * sC;
    } else {
        A += z * sA; B += z * sB; C += z * sC; if (R) R += z * sR;
    }
    const int bm = blockIdx.y * 128, bn = blockIdx.x * 64;
    if (BNT && causal && bn >= bm + 128) return;     // fully-masked causal tile
    const int tid = threadIdx.x;
    const int warp = tid >> 5, lane = tid & 31;
    const int wm = warp >> 1, wn = warp & 1;          // 4 warps in M, 2 in N

    const int rA = ((lane >> 1) & 3) ^ (((lane >> 4) & 1) << 1);
    const int rB = BNT ? ((lane >> 1) & 3)
                       : (((lane >> 1) & 3) ^ ((lane >> 3) & 1));
    const int4 oA = rotl4(make_int4(0, 4, 8, 12), rA);
    const int4 oB = BNT ? rotl4(make_int4(0, 2, 4, 6), rB)
                        : rotl4(make_int4(0, 8, 16, 24), rB);

    const float* gA[4];
#pragma unroll
    for (int i = 0; i < 4; i++) {
        int idx = tid + i * 256;
        int m = idx >> 3, k = (idx & 7) * 4;
        gA[i] = A + (long long)(bm + m) * lda + k;
    }
    const float* gB[2];
#pragma unroll
    for (int i = 0; i < 2; i++) {
        int idx = tid + i * 256;
        if (BNT) { int n = idx >> 3, k = (idx & 7) * 4; gB[i] = B + (long long)(bn + n) * ldb + k; }
        else     { int k = idx >> 4, n = (idx & 15) * 4; gB[i] = B + (long long)k * ldb + bn + n; }
    }
    const long long gBstep = BNT ? 32 : 32LL * ldb;

    int wa[4];
#pragma unroll
    for (int i = 0; i < 4; i++) {
        int idx = tid + i * 256;
        int m = idx >> 3, kb = (idx & 7) * 4;
        int mt = m >> 4, ks = kb >> 3, mm = m & 15;
        int ln = (mm & 7) * 4;
        int rg = (mm >> 3) + 2 * ((kb & 7) >> 2);
        wa[i] = ((mt * 4 + ks) * 32 + ln) * 4 + rg;
    }
    int wb[2];
#pragma unroll
    for (int i = 0; i < 2; i++) {
        int idx = tid + i * 256;
        if (BNT) {
            int n = idx >> 3, kb = (idx & 7) * 4;
            int nt = n >> 3, ks = kb >> 3;
            int ln = (n & 7) * 4;
            int rg = (kb & 7) >> 2;
            wb[i] = ((nt * 4 + ks) * 32 + ln) * 2 + rg;
        } else {
            int k = idx >> 4, nb = (idx & 15) * 4;
            int nt = nb >> 3, ks = k >> 3;
            int ln = (nb & 7) * 4 + (k & 3);
            int rg = (k & 7) >> 2;
            wb[i] = ((nt * 4 + ks) * 32 + ln) * 2 + rg;
        }
    }

    int la[2], lb[4];
#pragma unroll
    for (int mt = 0; mt < 2; mt++) la[mt] = ((wm * 2 + mt) * 4) * 32 + lane;
#pragma unroll
    for (int nt = 0; nt < 4; nt++) lb[nt] = ((wn * 4 + nt) * 4) * 32 + lane;

    float4 pa[4];
    float4 pb[2];

    auto gload = [&]() {
#pragma unroll
        for (int i = 0; i < 4; i++) { pa[i] = *(const float4*)gA[i]; gA[i] += 32; }
#pragma unroll
        for (int i = 0; i < 2; i++) { pb[i] = *(const float4*)gB[i]; gB[i] += gBstep; }
    };
    auto sts = [&](int buf) {
        int ab = buf << 12;
        int bb = buf << 11;
#pragma unroll
        for (int i = 0; i < 4; i++) {
            float4 t = rotl4(pa[i], rA);
            int base = ab + wa[i];
            asw[base + oA.x] = t.x;
            asw[base + oA.y] = t.y;
            asw[base + oA.z] = t.z;
            asw[base + oA.w] = t.w;
        }
#pragma unroll
        for (int i = 0; i < 2; i++) {
            float4 t = rotl4(pb[i], rB);
            int base = bb + wb[i];
            bsw[base + oB.x] = t.x;
            bsw[base + oB.y] = t.y;
            bsw[base + oB.z] = t.z;
            bsw[base + oB.w] = t.w;
        }
    };

    float acc[2][4][4] = {};
    const int Keff = (!BNT && causal) ? (bm + 128 < K ? bm + 128 : K) : K;
    const int nc = Keff >> 5;

    gload();
    sts(0);
    if (nc > 1) gload();
    __syncthreads();

    for (int c = 0; c < nc; c++) {
        if (c + 1 < nc) sts((c + 1) & 1);
        if (c + 2 < nc) gload();
        int buf = c & 1;
        int abase = buf << 10;
        int bbase = buf << 10;
#pragma unroll
        for (int ks = 0; ks < 4; ks++) {
            uint4 ah[2], al[2]; uint2 bh[4], bl[4];
#pragma unroll
            for (int mt = 0; mt < 2; mt++) {
                float4 ar = ((const float4*)As)[abase + la[mt] + ks * 32];
                split1(ar.x, ah[mt].x, al[mt].x);
                split1(ar.y, ah[mt].y, al[mt].y);
                split1(ar.z, ah[mt].z, al[mt].z);
                split1(ar.w, ah[mt].w, al[mt].w);
            }
#pragma unroll
            for (int nt = 0; nt < 4; nt++) {
                float2 br = ((const float2*)Bs)[bbase + lb[nt] + ks * 32];
                split1(br.x, bh[nt].x, bl[nt].x);
                split1(br.y, bh[nt].y, bl[nt].y);
            }
#pragma unroll
            for (int mt = 0; mt < 2; mt++)
#pragma unroll
                for (int nt = 0; nt < 4; nt++) {
                    float* a4 = acc[mt][nt];
                    MMA_TF32(a4[0], a4[1], a4[2], a4[3],
                             ah[mt].x, ah[mt].y, ah[mt].z, ah[mt].w, bl[nt].x, bl[nt].y);
                    MMA_TF32(a4[0], a4[1], a4[2], a4[3],
                             al[mt].x, al[mt].y, al[mt].z, al[mt].w, bh[nt].x, bh[nt].y);
                    MMA_TF32(a4[0], a4[1], a4[2], a4[3],
                             ah[mt].x, ah[mt].y, ah[mt].z, ah[mt].w, bh[nt].x, bh[nt].y);
                }
        }
        __syncthreads();
    }

    const int g = lane >> 2, t = lane & 3;
#pragma unroll
    for (int mt = 0; mt < 2; mt++) {
        int r0 = bm + wm * 32 + mt * 16 + g;
#pragma unroll
        for (int nt = 0; nt < 4; nt++) {
            int c0 = bn + wn * 32 + nt * 8 + t * 2;
            float vv[4] = {acc[mt][nt][0] * alpha, acc[mt][nt][1] * alpha,
                           acc[mt][nt][2] * alpha, acc[mt][nt][3] * alpha};
            if (act) {
#pragma unroll
                for (int q = 0; q < 4; q++) {
                    float v = vv[q];
                    float th = tanhf(0.7978845608028654f * (v + 0.044715f * v * v * v));
                    vv[q] = 0.5f * v * (1.f + th);
                }
            }
            if (R) {
                float2 r0v = *(const float2*)(R + (long long)r0 * ldr + c0);
                float2 r1v = *(const float2*)(R + (long long)(r0 + 8) * ldr + c0);
                vv[0] += r0v.x; vv[1] += r0v.y; vv[2] += r1v.x; vv[3] += r1v.y;
            }
            *(float2*)(C + (long long)r0 * ldc + c0) = make_float2(vv[0], vv[1]);
            *(float2*)(C + (long long)(r0 + 8) * ldc + c0) = make_float2(vv[2], vv[3]);
        }
    }
}

// ---- 64x64 / 128-thread variant: for small (occupancy-starved) grids ----
template<bool BNT>
__global__ void __launch_bounds__(128, 4)
gemm64_tf32x3(const float* __restrict__ A, const float* __restrict__ B,
              float* __restrict__ C, const float* __restrict__ R,
              int M, int N, int K, int lda, int ldb, int ldc, int ldr,
              long long sA, long long sB, long long sC, long long sR,
              float alpha, int act, int causal,
              int zsplit, long long sA2, long long sB2, long long sC2)
{
    __shared__ float4 As[2][512];
    __shared__ float2 Bs[2][1024];
    float* asw = (float*)As;
    float* bsw = (float*)Bs;

    int z = blockIdx.z;
    if (zsplit) {
        int zh = z >> 3, zl = z & 7;
        A += zh * sA2 + zl * sA;
        B += zh * sB2 + zl * sB;
        C += zh * sC2 + zl * sC;
    } else {
        A += z * sA; B += z * sB; C += z * sC; if (R) R += z * sR;
    }
    const int bm = blockIdx.y * 64, bn = blockIdx.x * 64;
    if (BNT && causal && bn >= bm + 64) return;
    const int tid = threadIdx.x;
    const int warp = tid >> 5, lane = tid & 31;
    const int wm = warp >> 1, wn = warp & 1;          // 2 warps in M, 2 in N

    const int rA = ((lane >> 1) & 3) ^ (((lane >> 4) & 1) << 1);
    const int rB = BNT ? ((lane >> 1) & 3)
                       : (((lane >> 1) & 3) ^ ((lane >> 3) & 1));
    const int4 oA = rotl4(make_int4(0, 4, 8, 12), rA);
    const int4 oB = BNT ? rotl4(make_int4(0, 2, 4, 6), rB)
                        : rotl4(make_int4(0, 8, 16, 24), rB);

    const float* gA[4];
#pragma unroll
    for (int i = 0; i < 4; i++) {
        int idx = tid + i * 128;
        int m = idx >> 3, k = (idx & 7) * 4;
        gA[i] = A + (long long)(bm + m) * lda + k;
    }
    const float* gB[4];
#pragma unroll
    for (int i = 0; i < 4; i++) {
        int idx = tid + i * 128;
        if (BNT) { int n = idx >> 3, k = (idx & 7) * 4; gB[i] = B + (long long)(bn + n) * ldb + k; }
        else     { int k = idx >> 4, n = (idx & 15) * 4; gB[i] = B + (long long)k * ldb + bn + n; }
    }
    const long long gBstep = BNT ? 32 : 32LL * ldb;

    int wa[4];
#pragma unroll
    for (int i = 0; i < 4; i++) {
        int idx = tid + i * 128;
        int m = idx >> 3, kb = (idx & 7) * 4;
        int mt = m >> 4, ks = kb >> 3, mm = m & 15;
        int ln = (mm & 7) * 4;
        int rg = (mm >> 3) + 2 * ((kb & 7) >> 2);
        wa[i] = ((mt * 4 + ks) * 32 + ln) * 4 + rg;
    }
    int wb[4];
#pragma unroll
    for (int i = 0; i < 4; i++) {
        int idx = tid + i * 128;
        if (BNT) {
            int n = idx >> 3, kb = (idx & 7) * 4;
            int nt = n >> 3, ks = kb >> 3;
            int ln = (n & 7) * 4;
            int rg = (kb & 7) >> 2;
            wb[i] = ((nt * 4 + ks) * 32 + ln) * 2 + rg;
        } else {
            int k = idx >> 4, nb = (idx & 15) * 4;
            int nt = nb >> 3, ks = k >> 3;
            int ln = (nb & 7) * 4 + (k & 3);
            int rg = (k & 7) >> 2;
            wb[i] = ((nt * 4 + ks) * 32 + ln) * 2 + rg;
        }
    }

    int la[2], lb[4];
#pragma unroll
    for (int mt = 0; mt < 2; mt++) la[mt] = ((wm * 2 + mt) * 4) * 32 + lane;
#pragma unroll
    for (int nt = 0; nt < 4; nt++) lb[nt] = ((wn * 4 + nt) * 4) * 32 + lane;

    float4 pa[4];
    float4 pb[4];

    auto gload = [&]() {
#pragma unroll
        for (int i = 0; i < 4; i++) { pa[i] = *(const float4*)gA[i]; gA[i] += 32; }
#pragma unroll
        for (int i = 0; i < 4; i++) { pb[i] = *(const float4*)gB[i]; gB[i] += gBstep; }
    };
    auto sts = [&](int buf) {
        int ab = buf << 11;
        int bb = buf << 11;
#pragma unroll
        for (int i = 0; i < 4; i++) {
            float4 t = rotl4(pa[i], rA);
            int base = ab + wa[i];
            asw[base + oA.x] = t.x;
            asw[base + oA.y] = t.y;
            asw[base + oA.z] = t.z;
            asw[base + oA.w] = t.w;
        }
#pragma unroll
        for (int i = 0; i < 4; i++) {
            float4 t = rotl4(pb[i], rB);
            int base = bb + wb[i];
            bsw[base + oB.x] = t.x;
            bsw[base + oB.y] = t.y;
            bsw[base + oB.z] = t.z;
            bsw[base + oB.w] = t.w;
        }
    };

    float acc[2][4][4] = {};
    const int Keff = (!BNT && causal) ? (bm + 64 < K ? bm + 64 : K) : K;
    const int nc = Keff >> 5;

    gload();
    sts(0);
    if (nc > 1) gload();
    __syncthreads();

    for (int c = 0; c < nc; c++) {
        if (c + 1 < nc) sts((c + 1) & 1);
        if (c + 2 < nc) gload();
        int buf = c & 1;
        int abase = buf << 9;
        int bbase = buf << 10;
#pragma unroll
        for (int ks = 0; ks < 4; ks++) {
            uint4 ah[2], al[2]; uint2 bh[4], bl[4];
#pragma unroll
            for (int mt = 0; mt < 2; mt++) {
                float4 ar = ((const float4*)As)[abase + la[mt] + ks * 32];
                split1(ar.x, ah[mt].x, al[mt].x);
                split1(ar.y, ah[mt].y, al[mt].y);
                split1(ar.z, ah[mt].z, al[mt].z);
                split1(ar.w, ah[mt].w, al[mt].w);
            }
#pragma unroll
            for (int nt = 0; nt < 4; nt++) {
                float2 br = ((const float2*)Bs)[bbase + lb[nt] + ks * 32];
                split1(br.x, bh[nt].x, bl[nt].x);
                split1(br.y, bh[nt].y, bl[nt].y);
            }
#pragma unroll
            for (int mt = 0; mt < 2; mt++)
#pragma unroll
                for (int nt = 0; nt < 4; nt++) {
                    float* a4 = acc[mt][nt];
                    MMA_TF32(a4[0], a4[1], a4[2], a4[3],
                             ah[mt].x, ah[mt].y, ah[mt].z, ah[mt].w, bl[nt].x, bl[nt].y);
                    MMA_TF32(a4[0], a4[1], a4[2], a4[3],
                             al[mt].x, al[mt].y, al[mt].z, al[mt].w, bh[nt].x, bh[nt].y);
                    MMA_TF32(a4[0], a4[1], a4[2], a4[3],
                             ah[mt].x, ah[mt].y, ah[mt].z, ah[mt].w, bh[nt].x, bh[nt].y);
                }
        }
        __syncthreads();
    }

    const int g = lane >> 2, t = lane & 3;
#pragma unroll
    for (int mt = 0; mt < 2; mt++) {
        int r0 = bm + wm * 32 + mt * 16 + g;
#pragma unroll
        for (int nt = 0; nt < 4; nt++) {
            int c0 = bn + wn * 32 + nt * 8 + t * 2;
            float vv[4] = {acc[mt][nt][0] * alpha, acc[mt][nt][1] * alpha,
                           acc[mt][nt][2] * alpha, acc[mt][nt][3] * alpha};
            if (act) {
#pragma unroll
                for (int q = 0; q < 4; q++) {
                    float v = vv[q];
                    float th = tanhf(0.7978845608028654f * (v + 0.044715f * v * v * v));
                    vv[q] = 0.5f * v * (1.f + th);
                }
            }
            if (R) {
                float2 r0v = *(const float2*)(R + (long long)r0 * ldr + c0);
                float2 r1v = *(const float2*)(R + (long long)(r0 + 8) * ldr + c0);
                vv[0] += r0v.x; vv[1] += r0v.y; vv[2] += r1v.x; vv[3] += r1v.y;
            }
            *(float2*)(C + (long long)r0 * ldc + c0) = make_float2(vv[0], vv[1]);
            *(float2*)(C + (long long)(r0 + 8) * ldc + c0) = make_float2(vv[2], vv[3]);
        }
    }
}

// ---------------- fallback SIMT NT gemm (router: N=9) ----------------
__global__ void gemm_nt(const float* __restrict__ A, const float* __restrict__ B,
                        float* __restrict__ C,
                        int M, int N, int K, int lda, int ldb, int ldc)
{
    int bm = blockIdx.y * 64, bn = blockIdx.x * 64;
    __shared__ float As[16][65], Bs[16][65];
    int tid = threadIdx.x;
    int tr = tid >> 4, tc = tid & 15;
    float acc[4][4] = {};
    for (int k0 = 0; k0 < K; k0 += 16) {
        for (int i = tid; i < 64 * 16; i += 256) {
            int m = i >> 4, k = i & 15;
            float v = 0.f;
            if (bm + m < M && k0 + k < K) v = A[(long long)(bm + m) * lda + k0 + k];
            As[k][m] = v;
        }
        for (int i = tid; i < 64 * 16; i += 256) {
            int n = i >> 4, k = i & 15;
            float v = 0.f;
            if (bn + n < N && k0 + k < K) v = B[(long long)(bn + n) * ldb + k0 + k];
            Bs[k][n] = v;
        }
        __syncthreads();
#pragma unroll
        for (int k = 0; k < 16; k++) {
            float a[4], b[4];
#pragma unroll
            for (int i = 0; i < 4; i++) a[i] = As[k][tr * 4 + i];
#pragma unroll
            for (int j = 0; j < 4; j++) b[j] = Bs[k][tc * 4 + j];
#pragma unroll
            for (int i = 0; i < 4; i++)
#pragma unroll
                for (int j = 0; j < 4; j++) acc[i][j] += a[i] * b[j];
        }
        __syncthreads();
    }
#pragma unroll
    for (int i = 0; i < 4; i++) {
        int m = bm + tr * 4 + i; if (m >= M) continue;
#pragma unroll
        for (int j = 0; j < 4; j++) {
            int n = bn + tc * 4 + j; if (n >= N) continue;
            C[(long long)m * ldc + n] = acc[i][j];
        }
    }
}

// ---------------- elementwise / reduction kernels ----------------
__global__ void embed_kernel(const int* __restrict__ ids, const float* __restrict__ ew)
{
    int idx = blockIdx.x * blockDim.x + threadIdx.x;
    if (idx < Tn * Dn) {
        int t = idx / Dn, d = idx % Dn;
        d_h[idx] = ew[(long long)ids[t] * Dn + d];
    }
}

__global__ void rope_table_kernel()
{
    int t = blockIdx.x; int i = threadIdx.x;                   // i in [0,32)
    double inv = pow(10000.0, -(2.0 * i) / 64.0);
    double f = (double)t * inv;
    float c = (float)cos(f), s = (float)sin(f);
    d_cos[t * DHn + i] = c; d_cos[t * DHn + i + 32] = c;
    d_sin[t * DHn + i] = s; d_sin[t * DHn + i + 32] = s;
}

__global__ void rmsnorm_kernel(const float* __restrict__ x, float* __restrict__ out,
                               const float* __restrict__ s)
{
    int r = blockIdx.x;
    const float* xr = x + (long long)r * Dn;
    float* orow = out + (long long)r * Dn;
    int tid = threadIdx.x;
    float ss = 0.f;
    for (int d = tid; d < Dn; d += 256) { float v = xr[d]; ss += v * v; }
    __shared__ float red[256];
    red[tid] = ss; __syncthreads();
    for (int st = 128; st > 0; st >>= 1) { if (tid < st) red[tid] += red[tid + st]; __syncthreads(); }
    float inv = rsqrtf(red[0] / Dn + 1e-6f);
    for (int d = tid; d < Dn; d += 256) orow[d] = xr[d] * inv * s[d];
}

// fused dispatch: gather h[slot] once -> write residual copy (xin) AND normalized
// expert input (eu, ordered [attn0..3 | ffn0..3]). Empty slots produce zero rows,
// matching the reference. Same per-row summation order as rmsnorm_kernel.
__global__ void gather_rmsnorm_kernel(const float* __restrict__ attn_ln,
                                      const float* __restrict__ ffn_ln)
{
    int c = blockIdx.x, e = blockIdx.y;
    int tok = d_slot[e * CAPn + c];
    const float* sr = (e & 1) ? ffn_ln + ((e - 1) >> 1) * Dn : attn_ln + (e >> 1) * Dn;
    int eidx = (e & 1) ? 4 + (e >> 1) : (e >> 1);
    float* xrow = d_xin + ((long long)e * CAPn + c) * Dn;
    float* erow = d_eu + ((long long)eidx * CAPn + c) * Dn;
    int tid = threadIdx.x;
    float v0 = 0.f, v1 = 0.f;
    if (tok >= 0) {
        v0 = d_h[(long long)tok * Dn + tid];
        v1 = d_h[(long long)tok * Dn + tid + 256];
    }
    __shared__ float red[256];
    red[tid] = v0 * v0 + v1 * v1;
    __syncthreads();
    for (int st = 128; st > 0; st >>= 1) { if (tid < st) red[tid] += red[tid + st]; __syncthreads(); }
    float inv = rsqrtf(red[0] / Dn + 1e-6f);
    xrow[tid] = v0; xrow[tid + 256] = v1;
    erow[tid] = v0 * inv * sr[tid];
    erow[tid + 256] = v1 * inv * sr[tid + 256];
}

// slot==nullptr: token id == row (backbone). Else gather cos/sin via slot[b*sstride + r];
// empty slots (tok<0) use cos=sin=0, matching the reference's zero-gathered rows.
__global__ void rope_apply_kernel(float* __restrict__ qkv, long long qbs,
                                  const int* __restrict__ slot, int sstride)
{
    int r = blockIdx.x, b = blockIdx.y;
    float* base = qkv + b * qbs + (long long)r * (3 * Dn);
    int tok = slot ? slot[b * sstride + r] : r;
    int hh = threadIdx.x >> 5, i = threadIdx.x & 31;
    float c = 0.f, s = 0.f;
    if (tok >= 0) { c = d_cos[tok * DHn + i]; s = d_sin[tok * DHn + i]; }
    float* q = base + hh * DHn;
    float x1 = q[i], x2 = q[i + 32];
    q[i] = x1 * c - x2 * s;
    q[i + 32] = x2 * c + x1 * s;
    float* k = base + Dn + hh * DHn;
    x1 = k[i]; x2 = k[i + 32];
    k[i] = x1 * c - x2 * s;
    k[i + 32] = x2 * c + x1 * s;
}

// causal softmax, single global pass; row cached in registers. Zero-fills to next
// 128 boundary (superset of what either causal AV tile variant reads).
__global__ void softmax_causal(float* __restrict__ sc, int C)
{
    int r = blockIdx.x; long long b = blockIdx.y;
    float* row = sc + b * (long long)C * C + (long long)r * C;
    int tid = threadIdx.x;
    __shared__ float red[256];
    float v[8];
    float mx = -3.4e38f;
#pragma unroll
    for (int k = 0; k < 8; k++) {
        int j = tid + (k << 8);
        if (j < C && j <= r) { v[k] = row[j]; mx = fmaxf(mx, v[k]); }
    }
    red[tid] = mx; __syncthreads();
    for (int st = 128; st > 0; st >>= 1) { if (tid < st) red[tid] = fmaxf(red[tid], red[tid + st]); __syncthreads(); }
    mx = red[0]; __syncthreads();
    float sum = 0.f;
#pragma unroll
    for (int k = 0; k < 8; k++) {
        int j = tid + (k << 8);
        if (j < C && j <= r) { float e = expf(v[k] - mx); v[k] = e; sum += e; }
    }
    red[tid] = sum; __syncthreads();
    for (int st = 128; st > 0; st >>= 1) { if (tid < st) red[tid] += red[tid + st]; __syncthreads(); }
    float inv = 1.f / red[0];
    int lim = ((r >> 7) + 1) << 7;
#pragma unroll
    for (int k = 0; k < 8; k++) {
        int j = tid + (k << 8);
        if (j < lim) row[j] = (j <= r) ? v[k] * inv : 0.f;
    }
}

__global__ void router_post_kernel()
{
    int t = blockIdx.x * blockDim.x + threadIdx.x;
    if (t >= Tn) return;
    float lg[9];
#pragma unroll
    for (int e = 0; e < 9; e++) lg[e] = d_logits[t * 9 + e];
    int i1 = 0;
#pragma unroll
    for (int e = 1; e < 9; e++) if (lg[e] > lg[i1]) i1 = e;
    int i2 = -1;
#pragma unroll
    for (int e = 0; e < 9; e++) { if (e == i1) continue; if (i2 < 0 || lg[e] > lg[i2]) i2 = e; }
    float mx = lg[i1];
    float p[9]; float sum = 0.f;
#pragma unroll
    for (int e = 0; e < 9; e++) { p[e] = expf(lg[e] - mx); sum += p[e]; }
    float inv = 1.f / sum;
#pragma unroll
    for (int e = 0; e < NEn; e++) {
        float pe = p[e] * inv;
        d_probs8[t * NEn + e] = pe;
        bool m = (e == i1) || (e == i2);
        d_g[e * Tn + t] = m ? pe : -INFINITY;
    }
}

// exact jax.lax.top_k order via rank-by-comparison; gate vector tiled through smem.
__global__ void rank_kernel()
{
    int e = blockIdx.y;
    int t = blockIdx.x * 256 + threadIdx.x;
    float gt = d_g[e * Tn + t];
    __shared__ float gs[256];
    int rank = 0;
    for (int j0 = 0; j0 < Tn; j0 += 256) {
        gs[threadIdx.x] = d_g[e * Tn + j0 + threadIdx.x];
        __syncthreads();
#pragma unroll 8
        for (int jj = 0; jj < 256; jj++) {
            float gj = gs[jj];
            rank += (gj > gt) || (gj == gt && (j0 + jj) < t);
        }
        __syncthreads();
    }
    bool msk = !isinf(gt);
    if (rank < CAPn) d_slot[e * CAPn + rank] = msk ? t : -1;
    d_cof[e * Tn + t] = (rank < CAPn && msk) ? rank : -1;
}

__global__ void combine_kernel()
{
    int idx = blockIdx.x * blockDim.x + threadIdx.x;
    if (idx >= Tn * Dn) return;
    int t = idx / Dn, d = idx % Dn;
    float acc = 0.f, rho = 0.f;
#pragma unroll
    for (int e = 0; e < NEn; e++) {
        int c = d_cof[e * Tn + t];
        if (c >= 0) {
            float w = d_probs8[t * NEn + e];
            rho += w;
            acc += w * d_exout[((long long)e * CAPn + c) * Dn + d];
        }
    }
    float hv = d_h[idx];
    d_h[idx] = hv + acc - rho * hv;
}

// ---------------- host orchestration ----------------
extern "C" void kernel_launch(void* const* d_in, const int* in_sizes, int n_in,
                              void* d_out, int out_size)
{
    (void)in_sizes; (void)n_in; (void)out_size;
    const int*   ids      = (const int*)d_in[0];
    const float* embed_w  = (const float*)d_in[1];
    const float* router_w = (const float*)d_in[2];
    const float* attn_qkv = (const float*)d_in[3];
    const float* attn_o   = (const float*)d_in[4];
    const float* attn_ln  = (const float*)d_in[5];
    const float* ffn_w1   = (const float*)d_in[6];
    const float* ffn_w2   = (const float*)d_in[7];
    const float* ffn_ln   = (const float*)d_in[8];
    const float* bb_qkv   = (const float*)d_in[9];
    const float* bb_o     = (const float*)d_in[10];
    const float* bb_ln    = (const float*)d_in[11];
    const float* lnout_s  = (const float*)d_in[12];
    float* out = (float*)d_out;

    float *h, *u, *qkv, *att, *sc, *logits, *eu, *eqkv, *eatt, *ffh, *exout, *xin;
    int* slot;
    cudaGetSymbolAddress((void**)&h, d_h);
    cudaGetSymbolAddress((void**)&u, d_u);
    cudaGetSymbolAddress((void**)&qkv, d_qkv);
    cudaGetSymbolAddress((void**)&att, d_att);
    cudaGetSymbolAddress((void**)&sc, d_sc);
    cudaGetSymbolAddress((void**)&logits, d_logits);
    cudaGetSymbolAddress((void**)&eu, d_eu);
    cudaGetSymbolAddress((void**)&eqkv, d_eqkv);
    cudaGetSymbolAddress((void**)&eatt, d_eatt);
    cudaGetSymbolAddress((void**)&ffh, d_ffh);
    cudaGetSymbolAddress((void**)&exout, d_exout);
    cudaGetSymbolAddress((void**)&xin, d_xin);
    cudaGetSymbolAddress((void**)&slot, d_slot);

    // 128x64 variant (large grids)
    auto NT = [](const float* A, const float* B, float* C, const float* R,
                 int M, int N, int K, int lda, int ldb, int ldc, int ldr,
                 long long sA, long long sB, long long sC, long long sR, int nb,
                 float alpha, int act, int causal) {
        dim3 g(N / 64, M / 128, nb);
        gemm_tf32x3<true><<<g, 256>>>(A, B, C, R, M, N, K, lda, ldb, ldc, ldr,
                                      sA, sB, sC, sR, alpha, act, causal, 0, 0, 0, 0);
    };
    // 64x64 variant (small, occupancy-starved grids)
    auto NT64 = [](const float* A, const float* B, float* C, const float* R,
                   int M, int N, int K, int lda, int ldb, int ldc, int ldr,
                   long long sA, long long sB, long long sC, long long sR, int nb,
                   float alpha, int act, int causal) {
        dim3 g(N / 64, M / 64, nb);
        gemm64_tf32x3<true><<<g, 128>>>(A, B, C, R, M, N, K, lda, ldb, ldc, ldr,
                                        sA, sB, sC, sR, alpha, act, causal, 0, 0, 0, 0);
    };
    auto NN64 = [](const float* A, const float* B, float* C,
                   int M, int N, int K, int lda, int ldb, int ldc,
                   long long sA, long long sB, long long sC, int nb, int causal) {
        dim3 g(N / 64, M / 64, nb);
        gemm64_tf32x3<false><<<g, 128>>>(A, B, C, nullptr, M, N, K, lda, ldb, ldc, 0,
                                         sA, sB, sC, 0, 1.f, 0, causal, 0, 0, 0, 0);
    };

    // ---- backbone ----
    embed_kernel<<<(Tn * Dn + 255) / 256, 256>>>(ids, embed_w);
    rope_table_kernel<<<Tn, 32>>>();
    rmsnorm_kernel<<<Tn, 256>>>(h, u, bb_ln);
    NT(u, bb_qkv, qkv, nullptr, Tn, 3 * Dn, Dn, Dn, Dn, 3 * Dn, 0, 0, 0, 0, 0, 1, 1.f, 0, 0);
    rope_apply_kernel<<<dim3(Tn, 1), 256>>>(qkv, 0, nullptr, 0);
    NT(qkv, qkv + Dn, sc, nullptr, Tn, Tn, DHn, 3 * Dn, 3 * Dn, Tn, 0,
       64, 64, (long long)Tn * Tn, 0, NHn, 0.125f, 0, 1);
    softmax_causal<<<dim3(Tn, NHn), 256>>>(sc, Tn);
    NN64(sc, qkv + 2 * Dn, att, Tn, DHn, Tn, Tn, 3 * Dn, Dn,
         (long long)Tn * Tn, 64, 64, NHn, 1);
    NT64(att, bb_o, h, h, Tn, Dn, Dn, Dn, Dn, Dn, Dn, 0, 0, 0, 0, 1, 1.f, 0, 0);

    // ---- hops ----
    for (int hop = 0; hop < 2; hop++) {
        {   // router logits (N=9): SIMT fp32 path
            dim3 g(1, (Tn + 63) / 64, 1);
            gemm_nt<<<g, 256>>>(h, router_w + hop * 9 * Dn, logits,
                                Tn, 9, Dn, Dn, Dn, 9);
        }
        router_post_kernel<<<(Tn + 255) / 256, 256>>>();
        rank_kernel<<<dim3(Tn / 256, NEn), 256>>>();
        gather_rmsnorm_kernel<<<dim3(CAPn, NEn), 256>>>(attn_ln, ffn_ln);

        // attention experts (eu batches [0..4) ; weight index j = e/2)
        NT(eu, attn_qkv, eqkv, nullptr, CAPn, 3 * Dn, Dn, Dn, Dn, 3 * Dn, 0,
           (long long)CAPn * Dn, 3LL * Dn * Dn, (long long)CAPn * 3 * Dn, 0, 4, 1.f, 0, 0);
        rope_apply_kernel<<<dim3(CAPn, 4), 256>>>(eqkv, (long long)CAPn * 3 * Dn,
                                                  slot, 2 * CAPn);
        {   // merged scores: z = j*8 + head (128-tile; large grid)
            dim3 g(CAPn / 64, CAPn / 128, 32);
            gemm_tf32x3<true><<<g, 256>>>(eqkv, eqkv + Dn, sc, nullptr,
                CAPn, CAPn, DHn, 3 * Dn, 3 * Dn, CAPn, 0,
                64, 64, (long long)CAPn * CAPn, 0, 0.125f, 0, 1,
                1, 3LL * CAPn * Dn, 3LL * CAPn * Dn, 8LL * CAPn * CAPn);
        }
        softmax_causal<<<dim3(CAPn, 4 * NHn), 256>>>(sc, CAPn);
        {   // merged AV: z = j*8 + head (64-tile; small grid -> 256 CTAs)
            dim3 g(DHn / 64, CAPn / 64, 32);
            gemm64_tf32x3<false><<<g, 128>>>(sc, eqkv + 2 * Dn, eatt, nullptr,
                CAPn, DHn, CAPn, CAPn, 3 * Dn, Dn, 0,
                (long long)CAPn * CAPn, 64, 64, 0, 1.f, 0, 1,
                1, 8LL * CAPn * CAPn, 3LL * CAPn * Dn, (long long)CAPn * Dn);
        }
        NT64(eatt, attn_o, exout, xin, CAPn, Dn, Dn, Dn, Dn, Dn, Dn,
             (long long)CAPn * Dn, (long long)Dn * Dn, 2LL * CAPn * Dn, 2LL * CAPn * Dn, 4, 1.f, 0, 0);

        // ffn experts (eu batches [4..8)), gelu fused into w1 GEMM
        NT(eu + 4LL * CAPn * Dn, ffn_w1, ffh, nullptr, CAPn, 4 * Dn, Dn, Dn, Dn, 4 * Dn, 0,
           (long long)CAPn * Dn, 4LL * Dn * Dn, (long long)CAPn * 4 * Dn, 0, 4, 1.f, 1, 0);
        NT64(ffh, ffn_w2, exout + CAPn * Dn, xin + CAPn * Dn, CAPn, Dn, 4 * Dn,
             4 * Dn, 4 * Dn, Dn, Dn,
             (long long)CAPn * 4 * Dn, 4LL * Dn * Dn, 2LL * CAPn * Dn, 2LL * CAPn * Dn, 4, 1.f, 0, 0);

        combine_kernel<<<(Tn * Dn + 255) / 256, 256>>>();
    }

    // ---- final rmsnorm -> output ----
    rmsnorm_kernel<<<Tn, 256>>>(h, out, lnout_s);
}

// round 14
// speedup vs baseline: 1.0341x; 1.0341x over previous
#include <cuda_runtime.h>
#include <math.h>
#include <stdint.h>

namespace {
constexpr int Tn  = 2048;
constexpr int Dn  = 512;
constexpr int NHn = 8;
constexpr int DHn = 64;
constexpr int CAPn = 512;
constexpr int NEn = 8;
constexpr int WKS = 4;                       // w2 split-K factor
}

// ---------------- scratch (static device globals; no runtime allocation) ----------------
__device__ float d_h[Tn * Dn];
__device__ float d_u[Tn * Dn];
__device__ float d_qkv[Tn * 3 * Dn];
__device__ float d_att[Tn * Dn];
__device__ float d_cos[Tn * DHn];
__device__ float d_sin[Tn * DHn];
__device__ float d_sc[(size_t)NHn * Tn * Tn];
__device__ float d_logits[Tn * 9];
__device__ float d_probs8[Tn * NEn];
__device__ float d_g[NEn * Tn];
__device__ int   d_cof[NEn * Tn];
__device__ int   d_slot[NEn * CAPn];
__device__ float d_xin[NEn * CAPn * Dn];
__device__ float d_eu[NEn * CAPn * Dn];          // [attn0..3 | ffn0..3] normalized inputs
__device__ float d_eqkv[4 * CAPn * 3 * Dn];
__device__ float d_eatt[4 * CAPn * Dn];
__device__ float d_ffh[4 * CAPn * 4 * Dn];
__device__ float d_exout[NEn * CAPn * Dn];
__device__ float d_wpart[WKS * 4 * CAPn * Dn];   // w2 split-K partials [s][b][m][n]

// ======================= TF32x3 tensor-core GEMM (fp32-accurate) =======================
// 128x64 CTA tile, 256 threads (8 warps of 32x32) — measured-optimal config.
// C[M,N] = act( alpha * A * op(B) ) (+R).  A: row-major MxK (lda).
// BNT=true : B row-major NxK (ldb)  -> C = A * B^T
// BNT=false: B row-major KxN (ldb)  -> C = A * B
// causal (NT): skip output tiles fully above the diagonal (bn >= bm+128).
// causal (NN): clamp K to bm+128 (A columns beyond hold exact zeros).
// zsplit: batch index decomposes as z = zhi*8 + zlo with strides (s?2, s?1).
// kns>1: split-K mode. z = s*knb + zb; slice s covers K columns [s*kslice, (s+1)*kslice);
//        partial written to C + z*sC (R must be null; reduction adds residual).
__device__ __forceinline__ uint32_t f2tf32(float x) {
    uint32_t r; asm("cvt.rna.tf32.f32 %0, %1;" : "=r"(r) : "f"(x)); return r;
}
// hi: RNA-rounded tf32. lo: residual passed RAW — tensor core reads .tf32 operands
// as the top 19 bits (implicit RZ truncation); truncation error <= 2^-25 |v|.
__device__ __forceinline__ void split1(float v, uint32_t& hi, uint32_t& lo) {
    hi = f2tf32(v);
    lo = __float_as_uint(v - __uint_as_float(hi));
}
// cyclic rotate-left so that position j holds element (j+r)&3
__device__ __forceinline__ float4 rotl4(float4 t, int r) {
    if (r & 1) t = make_float4(t.y, t.z, t.w, t.x);
    if (r & 2) t = make_float4(t.z, t.w, t.x, t.y);
    return t;
}
__device__ __forceinline__ int4 rotl4(int4 t, int r) {
    if (r & 1) t = make_int4(t.y, t.z, t.w, t.x);
    if (r & 2) t = make_int4(t.z, t.w, t.x, t.y);
    return t;
}

#define MMA_TF32(c0,c1,c2,c3,a0,a1,a2,a3,b0,b1)                                  \
    asm volatile("mma.sync.aligned.m16n8k8.row.col.f32.tf32.tf32.f32 "           \
                 "{%0,%1,%2,%3}, {%4,%5,%6,%7}, {%8,%9}, {%0,%1,%2,%3};"         \
                 : "+f"(c0), "+f"(c1), "+f"(c2), "+f"(c3)                         \
                 : "r"(a0), "r"(a1), "r"(a2), "r"(a3), "r"(b0), "r"(b1))

template<bool BNT>
__global__ void __launch_bounds__(256, 2)
gemm_tf32x3(const float* __restrict__ A, const float* __restrict__ B,
            float* __restrict__ C, const float* __restrict__ R,
            int M, int N, int K, int lda, int ldb, int ldc, int ldr,
            long long sA, long long sB, long long sC, long long sR,
            float alpha, int act, int causal,
            int zsplit, long long sA2, long long sB2, long long sC2,
            int kns, int knb, int kslice)
{
    __shared__ float4 As[2][1024];
    __shared__ float2 Bs[2][1024];
    float* asw = (float*)As;
    float* bsw = (float*)Bs;

    int z = blockIdx.z;
    if (kns > 1) {
        int s = z / knb, zb = z % knb;
        A += zb * sA + s * kslice;           // K offset within row (row-major A)
        B += zb * sB + s * kslice;           // BNT: K offset within row
        C += (long long)z * sC;
        K = kslice;
    } else if (zsplit) {
        int zh = z >> 3, zl = z & 7;
        A += zh * sA2 + zl * sA;
        B += zh * sB2 + zl * sB;
        C += zh * sC2 + zl * sC;
    } else {
        A += z * sA; B += z * sB; C += z * sC; if (R) R += z * sR;
    }
    const int bm = blockIdx.y * 128, bn = blockIdx.x * 64;
    if (BNT && causal && bn >= bm + 128) return;     // fully-masked causal tile
    const int tid = threadIdx.x;
    const int warp = tid >> 5, lane = tid & 31;
    const int wm = warp >> 1, wn = warp & 1;          // 4 warps in M, 2 in N

    const int rA = ((lane >> 1) & 3) ^ (((lane >> 4) & 1) << 1);
    const int rB = BNT ? ((lane >> 1) & 3)
                       : (((lane >> 1) & 3) ^ ((lane >> 3) & 1));
    const int4 oA = rotl4(make_int4(0, 4, 8, 12), rA);
    const int4 oB = BNT ? rotl4(make_int4(0, 2, 4, 6), rB)
                        : rotl4(make_int4(0, 8, 16, 24), rB);

    const float* gA[4];
#pragma unroll
    for (int i = 0; i < 4; i++) {
        int idx = tid + i * 256;
        int m = idx >> 3, k = (idx & 7) * 4;
        gA[i] = A + (long long)(bm + m) * lda + k;
    }
    const float* gB[2];
#pragma unroll
    for (int i = 0; i < 2; i++) {
        int idx = tid + i * 256;
        if (BNT) { int n = idx >> 3, k = (idx & 7) * 4; gB[i] = B + (long long)(bn + n) * ldb + k; }
        else     { int k = idx >> 4, n = (idx & 15) * 4; gB[i] = B + (long long)k * ldb + bn + n; }
    }
    const long long gBstep = BNT ? 32 : 32LL * ldb;

    int wa[4];
#pragma unroll
    for (int i = 0; i < 4; i++) {
        int idx = tid + i * 256;
        int m = idx >> 3, kb = (idx & 7) * 4;
        int mt = m >> 4, ks = kb >> 3, mm = m & 15;
        int ln = (mm & 7) * 4;
        int rg = (mm >> 3) + 2 * ((kb & 7) >> 2);
        wa[i] = ((mt * 4 + ks) * 32 + ln) * 4 + rg;
    }
    int wb[2];
#pragma unroll
    for (int i = 0; i < 2; i++) {
        int idx = tid + i * 256;
        if (BNT) {
            int n = idx >> 3, kb = (idx & 7) * 4;
            int nt = n >> 3, ks = kb >> 3;
            int ln = (n & 7) * 4;
            int rg = (kb & 7) >> 2;
            wb[i] = ((nt * 4 + ks) * 32 + ln) * 2 + rg;
        } else {
            int k = idx >> 4, nb = (idx & 15) * 4;
            int nt = nb >> 3, ks = k >> 3;
            int ln = (nb & 7) * 4 + (k & 3);
            int rg = (k & 7) >> 2;
            wb[i] = ((nt * 4 + ks) * 32 + ln) * 2 + rg;
        }
    }

    int la[2], lb[4];
#pragma unroll
    for (int mt = 0; mt < 2; mt++) la[mt] = ((wm * 2 + mt) * 4) * 32 + lane;
#pragma unroll
    for (int nt = 0; nt < 4; nt++) lb[nt] = ((wn * 4 + nt) * 4) * 32 + lane;

    float4 pa[4];
    float4 pb[2];

    auto gload = [&]() {
#pragma unroll
        for (int i = 0; i < 4; i++) { pa[i] = *(const float4*)gA[i]; gA[i] += 32; }
#pragma unroll
        for (int i = 0; i < 2; i++) { pb[i] = *(const float4*)gB[i]; gB[i] += gBstep; }
    };
    auto sts = [&](int buf) {
        int ab = buf << 12;
        int bb = buf << 11;
#pragma unroll
        for (int i = 0; i < 4; i++) {
            float4 t = rotl4(pa[i], rA);
            int base = ab + wa[i];
            asw[base + oA.x] = t.x;
            asw[base + oA.y] = t.y;
            asw[base + oA.z] = t.z;
            asw[base + oA.w] = t.w;
        }
#pragma unroll
        for (int i = 0; i < 2; i++) {
            float4 t = rotl4(pb[i], rB);
            int base = bb + wb[i];
            bsw[base + oB.x] = t.x;
            bsw[base + oB.y] = t.y;
            bsw[base + oB.z] = t.z;
            bsw[base + oB.w] = t.w;
        }
    };

    float acc[2][4][4] = {};
    const int Keff = (!BNT && causal) ? (bm + 128 < K ? bm + 128 : K) : K;
    const int nc = Keff >> 5;

    gload();
    sts(0);
    if (nc > 1) gload();
    __syncthreads();

    for (int c = 0; c < nc; c++) {
        if (c + 1 < nc) sts((c + 1) & 1);
        if (c + 2 < nc) gload();
        int buf = c & 1;
        int abase = buf << 10;
        int bbase = buf << 10;
#pragma unroll
        for (int ks = 0; ks < 4; ks++) {
            uint4 ah[2], al[2]; uint2 bh[4], bl[4];
#pragma unroll
            for (int mt = 0; mt < 2; mt++) {
                float4 ar = ((const float4*)As)[abase + la[mt] + ks * 32];
                split1(ar.x, ah[mt].x, al[mt].x);
                split1(ar.y, ah[mt].y, al[mt].y);
                split1(ar.z, ah[mt].z, al[mt].z);
                split1(ar.w, ah[mt].w, al[mt].w);
            }
#pragma unroll
            for (int nt = 0; nt < 4; nt++) {
                float2 br = ((const float2*)Bs)[bbase + lb[nt] + ks * 32];
                split1(br.x, bh[nt].x, bl[nt].x);
                split1(br.y, bh[nt].y, bl[nt].y);
            }
#pragma unroll
            for (int mt = 0; mt < 2; mt++)
#pragma unroll
                for (int nt = 0; nt < 4; nt++) {
                    float* a4 = acc[mt][nt];
                    MMA_TF32(a4[0], a4[1], a4[2], a4[3],
                             ah[mt].x, ah[mt].y, ah[mt].z, ah[mt].w, bl[nt].x, bl[nt].y);
                    MMA_TF32(a4[0], a4[1], a4[2], a4[3],
                             al[mt].x, al[mt].y, al[mt].z, al[mt].w, bh[nt].x, bh[nt].y);
                    MMA_TF32(a4[0], a4[1], a4[2], a4[3],
                             ah[mt].x, ah[mt].y, ah[mt].z, ah[mt].w, bh[nt].x, bh[nt].y);
                }
        }
        __syncthreads();
    }

    const int g = lane >> 2, t = lane & 3;
#pragma unroll
    for (int mt = 0; mt < 2; mt++) {
        int r0 = bm + wm * 32 + mt * 16 + g;
#pragma unroll
        for (int nt = 0; nt < 4; nt++) {
            int c0 = bn + wn * 32 + nt * 8 + t * 2;
            float vv[4] = {acc[mt][nt][0] * alpha, acc[mt][nt][1] * alpha,
                           acc[mt][nt][2] * alpha, acc[mt][nt][3] * alpha};
            if (act) {
#pragma unroll
                for (int q = 0; q < 4; q++) {
                    float v = vv[q];
                    float th = tanhf(0.7978845608028654f * (v + 0.044715f * v * v * v));
                    vv[q] = 0.5f * v * (1.f + th);
                }
            }
            if (R) {
                float2 r0v = *(const float2*)(R + (long long)r0 * ldr + c0);
                float2 r1v = *(const float2*)(R + (long long)(r0 + 8) * ldr + c0);
                vv[0] += r0v.x; vv[1] += r0v.y; vv[2] += r1v.x; vv[3] += r1v.y;
            }
            *(float2*)(C + (long long)r0 * ldc + c0) = make_float2(vv[0], vv[1]);
            *(float2*)(C + (long long)(r0 + 8) * ldc + c0) = make_float2(vv[2], vv[3]);
        }
    }
}

// w2 split-K reduce: exout_ffn[b][m][n] = xin_ffn[b][m][n] + sum_s part[s][b][m][n]
__global__ void wpart_reduce()
{
    int idx = blockIdx.x * blockDim.x + threadIdx.x;
    if (idx >= 4 * CAPn * Dn) return;                  // idx = b*CAP*Dn + m*Dn + n
    int b = idx >> 18;
    int mn = idx & (CAPn * Dn - 1);
    float acc = d_xin[(long long)CAPn * Dn + (long long)b * 2 * CAPn * Dn + mn];
#pragma unroll
    for (int s = 0; s < WKS; s++)
        acc += d_wpart[((long long)s * 4 + b) * CAPn * Dn + mn];
    d_exout[(long long)CAPn * Dn + (long long)b * 2 * CAPn * Dn + mn] = acc;
}

// ---------------- fallback SIMT NT gemm (router: N=9) ----------------
__global__ void gemm_nt(const float* __restrict__ A, const float* __restrict__ B,
                        float* __restrict__ C,
                        int M, int N, int K, int lda, int ldb, int ldc)
{
    int bm = blockIdx.y * 64, bn = blockIdx.x * 64;
    __shared__ float As[16][65], Bs[16][65];
    int tid = threadIdx.x;
    int tr = tid >> 4, tc = tid & 15;
    float acc[4][4] = {};
    for (int k0 = 0; k0 < K; k0 += 16) {
        for (int i = tid; i < 64 * 16; i += 256) {
            int m = i >> 4, k = i & 15;
            float v = 0.f;
            if (bm + m < M && k0 + k < K) v = A[(long long)(bm + m) * lda + k0 + k];
            As[k][m] = v;
        }
        for (int i = tid; i < 64 * 16; i += 256) {
            int n = i >> 4, k = i & 15;
            float v = 0.f;
            if (bn + n < N && k0 + k < K) v = B[(long long)(bn + n) * ldb + k0 + k];
            Bs[k][n] = v;
        }
        __syncthreads();
#pragma unroll
        for (int k = 0; k < 16; k++) {
            float a[4], b[4];
#pragma unroll
            for (int i = 0; i < 4; i++) a[i] = As[k][tr * 4 + i];
#pragma unroll
            for (int j = 0; j < 4; j++) b[j] = Bs[k][tc * 4 + j];
#pragma unroll
            for (int i = 0; i < 4; i++)
#pragma unroll
                for (int j = 0; j < 4; j++) acc[i][j] += a[i] * b[j];
        }
        __syncthreads();
    }
#pragma unroll
    for (int i = 0; i < 4; i++) {
        int m = bm + tr * 4 + i; if (m >= M) continue;
#pragma unroll
        for (int j = 0; j < 4; j++) {
            int n = bn + tc * 4 + j; if (n >= N) continue;
            C[(long long)m * ldc + n] = acc[i][j];
        }
    }
}

// ---------------- elementwise / reduction kernels ----------------
__global__ void embed_kernel(const int* __restrict__ ids, const float* __restrict__ ew)
{
    int idx = blockIdx.x * blockDim.x + threadIdx.x;
    if (idx < Tn * Dn) {
        int t = idx / Dn, d = idx % Dn;
        d_h[idx] = ew[(long long)ids[t] * Dn + d];
    }
}

__global__ void rope_table_kernel()
{
    int t = blockIdx.x; int i = threadIdx.x;                   // i in [0,32)
    double inv = pow(10000.0, -(2.0 * i) / 64.0);
    double f = (double)t * inv;
    float c = (float)cos(f), s = (float)sin(f);
    d_cos[t * DHn + i] = c; d_cos[t * DHn + i + 32] = c;
    d_sin[t * DHn + i] = s; d_sin[t * DHn + i + 32] = s;
}

__global__ void rmsnorm_kernel(const float* __restrict__ x, float* __restrict__ out,
                               const float* __restrict__ s)
{
    int r = blockIdx.x;
    const float* xr = x + (long long)r * Dn;
    float* orow = out + (long long)r * Dn;
    int tid = threadIdx.x;
    float ss = 0.f;
    for (int d = tid; d < Dn; d += 256) { float v = xr[d]; ss += v * v; }
    __shared__ float red[256];
    red[tid] = ss; __syncthreads();
    for (int st = 128; st > 0; st >>= 1) { if (tid < st) red[tid] += red[tid + st]; __syncthreads(); }
    float inv = rsqrtf(red[0] / Dn + 1e-6f);
    for (int d = tid; d < Dn; d += 256) orow[d] = xr[d] * inv * s[d];
}

// fused dispatch: gather h[slot] once -> write residual copy (xin) AND normalized
// expert input (eu, ordered [attn0..3 | ffn0..3]). Empty slots produce zero rows,
// matching the reference. Same per-row summation order as rmsnorm_kernel.
__global__ void gather_rmsnorm_kernel(const float* __restrict__ attn_ln,
                                      const float* __restrict__ ffn_ln)
{
    int c = blockIdx.x, e = blockIdx.y;
    int tok = d_slot[e * CAPn + c];
    const float* sr = (e & 1) ? ffn_ln + ((e - 1) >> 1) * Dn : attn_ln + (e >> 1) * Dn;
    int eidx = (e & 1) ? 4 + (e >> 1) : (e >> 1);
    float* xrow = d_xin + ((long long)e * CAPn + c) * Dn;
    float* erow = d_eu + ((long long)eidx * CAPn + c) * Dn;
    int tid = threadIdx.x;
    float v0 = 0.f, v1 = 0.f;
    if (tok >= 0) {
        v0 = d_h[(long long)tok * Dn + tid];
        v1 = d_h[(long long)tok * Dn + tid + 256];
    }
    __shared__ float red[256];
    red[tid] = v0 * v0 + v1 * v1;
    __syncthreads();
    for (int st = 128; st > 0; st >>= 1) { if (tid < st) red[tid] += red[tid + st]; __syncthreads(); }
    float inv = rsqrtf(red[0] / Dn + 1e-6f);
    xrow[tid] = v0; xrow[tid + 256] = v1;
    erow[tid] = v0 * inv * sr[tid];
    erow[tid + 256] = v1 * inv * sr[tid + 256];
}

// slot==nullptr: token id == row (backbone). Else gather cos/sin via slot[b*sstride + r];
// empty slots (tok<0) use cos=sin=0, matching the reference's zero-gathered rows.
__global__ void rope_apply_kernel(float* __restrict__ qkv, long long qbs,
                                  const int* __restrict__ slot, int sstride)
{
    int r = blockIdx.x, b = blockIdx.y;
    float* base = qkv + b * qbs + (long long)r * (3 * Dn);
    int tok = slot ? slot[b * sstride + r] : r;
    int hh = threadIdx.x >> 5, i = threadIdx.x & 31;
    float c = 0.f, s = 0.f;
    if (tok >= 0) { c = d_cos[tok * DHn + i]; s = d_sin[tok * DHn + i]; }
    float* q = base + hh * DHn;
    float x1 = q[i], x2 = q[i + 32];
    q[i] = x1 * c - x2 * s;
    q[i + 32] = x2 * c + x1 * s;
    float* k = base + Dn + hh * DHn;
    x1 = k[i]; x2 = k[i + 32];
    k[i] = x1 * c - x2 * s;
    k[i + 32] = x2 * c + x1 * s;
}

// causal softmax, single global pass; row cached in registers. Zero-fills to next
// 128 boundary (all the causal-aware AV GEMM ever reads).
__global__ void softmax_causal(float* __restrict__ sc, int C)
{
    int r = blockIdx.x; long long b = blockIdx.y;
    float* row = sc + b * (long long)C * C + (long long)r * C;
    int tid = threadIdx.x;
    __shared__ float red[256];
    float v[8];
    float mx = -3.4e38f;
#pragma unroll
    for (int k = 0; k < 8; k++) {
        int j = tid + (k << 8);
        if (j < C && j <= r) { v[k] = row[j]; mx = fmaxf(mx, v[k]); }
    }
    red[tid] = mx; __syncthreads();
    for (int st = 128; st > 0; st >>= 1) { if (tid < st) red[tid] = fmaxf(red[tid], red[tid + st]); __syncthreads(); }
    mx = red[0]; __syncthreads();
    float sum = 0.f;
#pragma unroll
    for (int k = 0; k < 8; k++) {
        int j = tid + (k << 8);
        if (j < C && j <= r) { float e = expf(v[k] - mx); v[k] = e; sum += e; }
    }
    red[tid] = sum; __syncthreads();
    for (int st = 128; st > 0; st >>= 1) { if (tid < st) red[tid] += red[tid + st]; __syncthreads(); }
    float inv = 1.f / red[0];
    int lim = ((r >> 7) + 1) << 7;
#pragma unroll
    for (int k = 0; k < 8; k++) {
        int j = tid + (k << 8);
        if (j < lim) row[j] = (j <= r) ? v[k] * inv : 0.f;
    }
}

__global__ void router_post_kernel()
{
    int t = blockIdx.x * blockDim.x + threadIdx.x;
    if (t >= Tn) return;
    float lg[9];
#pragma unroll
    for (int e = 0; e < 9; e++) lg[e] = d_logits[t * 9 + e];
    int i1 = 0;
#pragma unroll
    for (int e = 1; e < 9; e++) if (lg[e] > lg[i1]) i1 = e;
    int i2 = -1;
#pragma unroll
    for (int e = 0; e < 9; e++) { if (e == i1) continue; if (i2 < 0 || lg[e] > lg[i2]) i2 = e; }
    float mx = lg[i1];
    float p[9]; float sum = 0.f;
#pragma unroll
    for (int e = 0; e < 9; e++) { p[e] = expf(lg[e] - mx); sum += p[e]; }
    float inv = 1.f / sum;
#pragma unroll
    for (int e = 0; e < NEn; e++) {
        float pe = p[e] * inv;
        d_probs8[t * NEn + e] = pe;
        bool m = (e == i1) || (e == i2);
        d_g[e * Tn + t] = m ? pe : -INFINITY;
    }
}

// exact jax.lax.top_k order via rank-by-comparison; gate vector tiled through smem.
__global__ void rank_kernel()
{
    int e = blockIdx.y;
    int t = blockIdx.x * 256 + threadIdx.x;
    float gt = d_g[e * Tn + t];
    __shared__ float gs[256];
    int rank = 0;
    for (int j0 = 0; j0 < Tn; j0 += 256) {
        gs[threadIdx.x] = d_g[e * Tn + j0 + threadIdx.x];
        __syncthreads();
#pragma unroll 8
        for (int jj = 0; jj < 256; jj++) {
            float gj = gs[jj];
            rank += (gj > gt) || (gj == gt && (j0 + jj) < t);
        }
        __syncthreads();
    }
    bool msk = !isinf(gt);
    if (rank < CAPn) d_slot[e * CAPn + rank] = msk ? t : -1;
    d_cof[e * Tn + t] = (rank < CAPn && msk) ? rank : -1;
}

__global__ void combine_kernel()
{
    int idx = blockIdx.x * blockDim.x + threadIdx.x;
    if (idx >= Tn * Dn) return;
    int t = idx / Dn, d = idx % Dn;
    float acc = 0.f, rho = 0.f;
#pragma unroll
    for (int e = 0; e < NEn; e++) {
        int c = d_cof[e * Tn + t];
        if (c >= 0) {
            float w = d_probs8[t * NEn + e];
            rho += w;
            acc += w * d_exout[((long long)e * CAPn + c) * Dn + d];
        }
    }
    float hv = d_h[idx];
    d_h[idx] = hv + acc - rho * hv;
}

// ---------------- host orchestration ----------------
extern "C" void kernel_launch(void* const* d_in, const int* in_sizes, int n_in,
                              void* d_out, int out_size)
{
    (void)in_sizes; (void)n_in; (void)out_size;
    const int*   ids      = (const int*)d_in[0];
    const float* embed_w  = (const float*)d_in[1];
    const float* router_w = (const float*)d_in[2];
    const float* attn_qkv = (const float*)d_in[3];
    const float* attn_o   = (const float*)d_in[4];
    const float* attn_ln  = (const float*)d_in[5];
    const float* ffn_w1   = (const float*)d_in[6];
    const float* ffn_w2   = (const float*)d_in[7];
    const float* ffn_ln   = (const float*)d_in[8];
    const float* bb_qkv   = (const float*)d_in[9];
    const float* bb_o     = (const float*)d_in[10];
    const float* bb_ln    = (const float*)d_in[11];
    const float* lnout_s  = (const float*)d_in[12];
    float* out = (float*)d_out;

    float *h, *u, *qkv, *att, *sc, *logits, *eu, *eqkv, *eatt, *ffh, *exout, *xin, *wpart;
    int* slot;
    cudaGetSymbolAddress((void**)&h, d_h);
    cudaGetSymbolAddress((void**)&u, d_u);
    cudaGetSymbolAddress((void**)&qkv, d_qkv);
    cudaGetSymbolAddress((void**)&att, d_att);
    cudaGetSymbolAddress((void**)&sc, d_sc);
    cudaGetSymbolAddress((void**)&logits, d_logits);
    cudaGetSymbolAddress((void**)&eu, d_eu);
    cudaGetSymbolAddress((void**)&eqkv, d_eqkv);
    cudaGetSymbolAddress((void**)&eatt, d_eatt);
    cudaGetSymbolAddress((void**)&ffh, d_ffh);
    cudaGetSymbolAddress((void**)&exout, d_exout);
    cudaGetSymbolAddress((void**)&xin, d_xin);
    cudaGetSymbolAddress((void**)&wpart, d_wpart);
    cudaGetSymbolAddress((void**)&slot, d_slot);

    auto NT = [](const float* A, const float* B, float* C, const float* R,
                 int M, int N, int K, int lda, int ldb, int ldc, int ldr,
                 long long sA, long long sB, long long sC, long long sR, int nb,
                 float alpha, int act, int causal) {
        dim3 g(N / 64, M / 128, nb);
        gemm_tf32x3<true><<<g, 256>>>(A, B, C, R, M, N, K, lda, ldb, ldc, ldr,
                                      sA, sB, sC, sR, alpha, act, causal, 0, 0, 0, 0, 0, 0, 0);
    };
    auto NN = [](const float* A, const float* B, float* C,
                 int M, int N, int K, int lda, int ldb, int ldc,
                 long long sA, long long sB, long long sC, int nb, int causal) {
        dim3 g(N / 64, M / 128, nb);
        gemm_tf32x3<false><<<g, 256>>>(A, B, C, nullptr, M, N, K, lda, ldb, ldc, 0,
                                       sA, sB, sC, 0, 1.f, 0, causal, 0, 0, 0, 0, 0, 0, 0);
    };

    // ---- backbone ----
    embed_kernel<<<(Tn * Dn + 255) / 256, 256>>>(ids, embed_w);
    rope_table_kernel<<<Tn, 32>>>();
    rmsnorm_kernel<<<Tn, 256>>>(h, u, bb_ln);
    NT(u, bb_qkv, qkv, nullptr, Tn, 3 * Dn, Dn, Dn, Dn, 3 * Dn, 0, 0, 0, 0, 0, 1, 1.f, 0, 0);
    rope_apply_kernel<<<dim3(Tn, 1), 256>>>(qkv, 0, nullptr, 0);
    NT(qkv, qkv + Dn, sc, nullptr, Tn, Tn, DHn, 3 * Dn, 3 * Dn, Tn, 0,
       64, 64, (long long)Tn * Tn, 0, NHn, 0.125f, 0, 1);
    softmax_causal<<<dim3(Tn, NHn), 256>>>(sc, Tn);
    NN(sc, qkv + 2 * Dn, att, Tn, DHn, Tn, Tn, 3 * Dn, Dn,
       (long long)Tn * Tn, 64, 64, NHn, 1);
    NT(att, bb_o, h, h, Tn, Dn, Dn, Dn, Dn, Dn, Dn, 0, 0, 0, 0, 1, 1.f, 0, 0);

    // ---- hops ----
    for (int hop = 0; hop < 2; hop++) {
        {   // router logits (N=9): SIMT fp32 path
            dim3 g(1, (Tn + 63) / 64, 1);
            gemm_nt<<<g, 256>>>(h, router_w + hop * 9 * Dn, logits,
                                Tn, 9, Dn, Dn, Dn, 9);
        }
        router_post_kernel<<<(Tn + 255) / 256, 256>>>();
        rank_kernel<<<dim3(Tn / 256, NEn), 256>>>();
        gather_rmsnorm_kernel<<<dim3(CAPn, NEn), 256>>>(attn_ln, ffn_ln);

        // attention experts (eu batches [0..4) ; weight index j = e/2)
        NT(eu, attn_qkv, eqkv, nullptr, CAPn, 3 * Dn, Dn, Dn, Dn, 3 * Dn, 0,
           (long long)CAPn * Dn, 3LL * Dn * Dn, (long long)CAPn * 3 * Dn, 0, 4, 1.f, 0, 0);
        rope_apply_kernel<<<dim3(CAPn, 4), 256>>>(eqkv, (long long)CAPn * 3 * Dn,
                                                  slot, 2 * CAPn);
        {   // merged scores: z = j*8 + head
            dim3 g(CAPn / 64, CAPn / 128, 32);
            gemm_tf32x3<true><<<g, 256>>>(eqkv, eqkv + Dn, sc, nullptr,
                CAPn, CAPn, DHn, 3 * Dn, 3 * Dn, CAPn, 0,
                64, 64, (long long)CAPn * CAPn, 0, 0.125f, 0, 1,
                1, 3LL * CAPn * Dn, 3LL * CAPn * Dn, 8LL * CAPn * CAPn, 0, 0, 0);
        }
        softmax_causal<<<dim3(CAPn, 4 * NHn), 256>>>(sc, CAPn);
        {   // merged AV: z = j*8 + head
            dim3 g(DHn / 64, CAPn / 128, 32);
            gemm_tf32x3<false><<<g, 256>>>(sc, eqkv + 2 * Dn, eatt, nullptr,
                CAPn, DHn, CAPn, CAPn, 3 * Dn, Dn, 0,
                (long long)CAPn * CAPn, 64, 64, 0, 1.f, 0, 1,
                1, 8LL * CAPn * CAPn, 3LL * CAPn * Dn, (long long)CAPn * Dn, 0, 0, 0);
        }
        NT(eatt, attn_o, exout, xin, CAPn, Dn, Dn, Dn, Dn, Dn, Dn,
           (long long)CAPn * Dn, (long long)Dn * Dn, 2LL * CAPn * Dn, 2LL * CAPn * Dn, 4, 1.f, 0, 0);

        // ffn experts (eu batches [4..8)), gelu fused into w1 GEMM
        NT(eu + 4LL * CAPn * Dn, ffn_w1, ffh, nullptr, CAPn, 4 * Dn, Dn, Dn, Dn, 4 * Dn, 0,
           (long long)CAPn * Dn, 4LL * Dn * Dn, (long long)CAPn * 4 * Dn, 0, 4, 1.f, 1, 0);
        {   // w2 with split-K=4: z = s*4 + b ; partials -> d_wpart, then reduce (+xin)
            dim3 g(Dn / 64, CAPn / 128, 4 * WKS);
            gemm_tf32x3<true><<<g, 256>>>(ffh, ffn_w2, wpart, nullptr,
                CAPn, Dn, 4 * Dn, 4 * Dn, 4 * Dn, Dn, 0,
                (long long)CAPn * 4 * Dn, 4LL * Dn * Dn, (long long)CAPn * Dn, 0,
                1.f, 0, 0,
                0, 0, 0, 0, WKS, 4, (4 * Dn) / WKS);
            wpart_reduce<<<(4 * CAPn * Dn + 255) / 256, 256>>>();
        }

        combine_kernel<<<(Tn * Dn + 255) / 256, 256>>>();
    }

    // ---- final rmsnorm -> output ----
    rmsnorm_kernel<<<Tn, 256>>>(h, out, lnout_s);
}

// round 15
// speedup vs baseline: 1.1282x; 1.0910x over previous
#include <cuda_runtime.h>
#include <math.h>
#include <stdint.h>

namespace {
constexpr int Tn  = 2048;
constexpr int Dn  = 512;
constexpr int NHn = 8;
constexpr int DHn = 64;
constexpr int CAPn = 512;
constexpr int NEn = 8;
}

// ---------------- scratch (static device globals; no runtime allocation) ----------------
__device__ float d_h[Tn * Dn];
__device__ float d_u[Tn * Dn];
__device__ float d_qkv[Tn * 3 * Dn];
__device__ float d_att[Tn * Dn];
__device__ float d_cos[Tn * DHn];
__device__ float d_sin[Tn * DHn];
__device__ float d_sc[(size_t)NHn * Tn * Tn];
__device__ float d_logits[Tn * 9];
__device__ float d_probs8[Tn * NEn];
__device__ float d_g[NEn * Tn];
__device__ int   d_cof[NEn * Tn];
__device__ int   d_slot[NEn * CAPn];
__device__ float d_xin[NEn * CAPn * Dn];
__device__ float d_eu[NEn * CAPn * Dn];          // [attn0..3 | ffn0..3] normalized inputs
__device__ float d_eqkv[4 * CAPn * 3 * Dn];
__device__ float d_eatt[4 * CAPn * Dn];
__device__ float d_ffh[4 * CAPn * 4 * Dn];
__device__ float d_exout[NEn * CAPn * Dn];

// ======================= TF32x3 tensor-core GEMM (fp32-accurate) =======================
// 128x64 CTA tile, 256 threads (8 warps of 32x32) — measured-optimal config.
// C[M,N] = act( alpha * A * op(B) ) (+R).  A: row-major MxK (lda).
// BNT=true : B row-major NxK (ldb)  -> C = A * B^T
// BNT=false: B row-major KxN (ldb)  -> C = A * B
// causal (NT): skip output tiles fully above the diagonal (bn >= bm+128).
// causal (NN): clamp K to bm+128 (A columns beyond hold exact zeros).
// zsplit: batch index decomposes as z = zhi*8 + zlo with strides (s?2, s?1).
__device__ __forceinline__ uint32_t f2tf32(float x) {
    uint32_t r; asm("cvt.rna.tf32.f32 %0, %1;" : "=r"(r) : "f"(x)); return r;
}
// hi: RNA-rounded tf32. lo: residual passed RAW — tensor core reads .tf32 operands
// as the top 19 bits (implicit RZ truncation); truncation error <= 2^-25 |v|.
__device__ __forceinline__ void split1(float v, uint32_t& hi, uint32_t& lo) {
    hi = f2tf32(v);
    lo = __float_as_uint(v - __uint_as_float(hi));
}
// cyclic rotate-left so that position j holds element (j+r)&3
__device__ __forceinline__ float4 rotl4(float4 t, int r) {
    if (r & 1) t = make_float4(t.y, t.z, t.w, t.x);
    if (r & 2) t = make_float4(t.z, t.w, t.x, t.y);
    return t;
}
__device__ __forceinline__ int4 rotl4(int4 t, int r) {
    if (r & 1) t = make_int4(t.y, t.z, t.w, t.x);
    if (r & 2) t = make_int4(t.z, t.w, t.x, t.y);
    return t;
}

#define MMA_TF32(c0,c1,c2,c3,a0,a1,a2,a3,b0,b1)                                  \
    asm volatile("mma.sync.aligned.m16n8k8.row.col.f32.tf32.tf32.f32 "           \
                 "{%0,%1,%2,%3}, {%4,%5,%6,%7}, {%8,%9}, {%0,%1,%2,%3};"         \
                 : "+f"(c0), "+f"(c1), "+f"(c2), "+f"(c3)                         \
                 : "r"(a0), "r"(a1), "r"(a2), "r"(a3), "r"(b0), "r"(b1))

template<bool BNT>
__global__ void __launch_bounds__(256, 2)
gemm_tf32x3(const float* __restrict__ A, const float* __restrict__ B,
            float* __restrict__ C, const float* __restrict__ R,
            int M, int N, int K, int lda, int ldb, int ldc, int ldr,
            long long sA, long long sB, long long sC, long long sR,
            float alpha, int act, int causal,
            int zsplit, long long sA2, long long sB2, long long sC2)
{
    __shared__ float4 As[2][1024];
    __shared__ float2 Bs[2][1024];
    float* asw = (float*)As;
    float* bsw = (float*)Bs;

    int z = blockIdx.z;
    if (zsplit) {
        int zh = z >> 3, zl = z & 7;
        A += zh * sA2 + zl * sA;
        B += zh * sB2 + zl * sB;
        C += zh * sC2 + zl * sC;
    } else {
        A += z * sA; B += z * sB; C += z * sC; if (R) R += z * sR;
    }
    const int bm = blockIdx.y * 128, bn = blockIdx.x * 64;
    if (BNT && causal && bn >= bm + 128) return;     // fully-masked causal tile
    const int tid = threadIdx.x;
    const int warp = tid >> 5, lane = tid & 31;
    const int wm = warp >> 1, wn = warp & 1;          // 4 warps in M, 2 in N

    const int rA = ((lane >> 1) & 3) ^ (((lane >> 4) & 1) << 1);
    const int rB = BNT ? ((lane >> 1) & 3)
                       : (((lane >> 1) & 3) ^ ((lane >> 3) & 1));
    const int4 oA = rotl4(make_int4(0, 4, 8, 12), rA);
    const int4 oB = BNT ? rotl4(make_int4(0, 2, 4, 6), rB)
                        : rotl4(make_int4(0, 8, 16, 24), rB);

    const float* gA[4];
#pragma unroll
    for (int i = 0; i < 4; i++) {
        int idx = tid + i * 256;
        int m = idx >> 3, k = (idx & 7) * 4;
        gA[i] = A + (long long)(bm + m) * lda + k;
    }
    const float* gB[2];
#pragma unroll
    for (int i = 0; i < 2; i++) {
        int idx = tid + i * 256;
        if (BNT) { int n = idx >> 3, k = (idx & 7) * 4; gB[i] = B + (long long)(bn + n) * ldb + k; }
        else     { int k = idx >> 4, n = (idx & 15) * 4; gB[i] = B + (long long)k * ldb + bn + n; }
    }
    const long long gBstep = BNT ? 32 : 32LL * ldb;

    int wa[4];
#pragma unroll
    for (int i = 0; i < 4; i++) {
        int idx = tid + i * 256;
        int m = idx >> 3, kb = (idx & 7) * 4;
        int mt = m >> 4, ks = kb >> 3, mm = m & 15;
        int ln = (mm & 7) * 4;
        int rg = (mm >> 3) + 2 * ((kb & 7) >> 2);
        wa[i] = ((mt * 4 + ks) * 32 + ln) * 4 + rg;
    }
    int wb[2];
#pragma unroll
    for (int i = 0; i < 2; i++) {
        int idx = tid + i * 256;
        if (BNT) {
            int n = idx >> 3, kb = (idx & 7) * 4;
            int nt = n >> 3, ks = kb >> 3;
            int ln = (n & 7) * 4;
            int rg = (kb & 7) >> 2;
            wb[i] = ((nt * 4 + ks) * 32 + ln) * 2 + rg;
        } else {
            int k = idx >> 4, nb = (idx & 15) * 4;
            int nt = nb >> 3, ks = k >> 3;
            int ln = (nb & 7) * 4 + (k & 3);
            int rg = (k & 7) >> 2;
            wb[i] = ((nt * 4 + ks) * 32 + ln) * 2 + rg;
        }
    }

    int la[2], lb[4];
#pragma unroll
    for (int mt = 0; mt < 2; mt++) la[mt] = ((wm * 2 + mt) * 4) * 32 + lane;
#pragma unroll
    for (int nt = 0; nt < 4; nt++) lb[nt] = ((wn * 4 + nt) * 4) * 32 + lane;

    float4 pa[4];
    float4 pb[2];

    auto gload = [&]() {
#pragma unroll
        for (int i = 0; i < 4; i++) { pa[i] = *(const float4*)gA[i]; gA[i] += 32; }
#pragma unroll
        for (int i = 0; i < 2; i++) { pb[i] = *(const float4*)gB[i]; gB[i] += gBstep; }
    };
    auto sts = [&](int buf) {
        int ab = buf << 12;
        int bb = buf << 11;
#pragma unroll
        for (int i = 0; i < 4; i++) {
            float4 t = rotl4(pa[i], rA);
            int base = ab + wa[i];
            asw[base + oA.x] = t.x;
            asw[base + oA.y] = t.y;
            asw[base + oA.z] = t.z;
            asw[base + oA.w] = t.w;
        }
#pragma unroll
        for (int i = 0; i < 2; i++) {
            float4 t = rotl4(pb[i], rB);
            int base = bb + wb[i];
            bsw[base + oB.x] = t.x;
            bsw[base + oB.y] = t.y;
            bsw[base + oB.z] = t.z;
            bsw[base + oB.w] = t.w;
        }
    };

    float acc[2][4][4] = {};
    const int Keff = (!BNT && causal) ? (bm + 128 < K ? bm + 128 : K) : K;
    const int nc = Keff >> 5;

    gload();
    sts(0);
    if (nc > 1) gload();
    __syncthreads();

    for (int c = 0; c < nc; c++) {
        if (c + 1 < nc) sts((c + 1) & 1);
        if (c + 2 < nc) gload();
        int buf = c & 1;
        int abase = buf << 10;
        int bbase = buf << 10;
#pragma unroll
        for (int ks = 0; ks < 4; ks++) {
            uint4 ah[2], al[2]; uint2 bh[4], bl[4];
#pragma unroll
            for (int mt = 0; mt < 2; mt++) {
                float4 ar = ((const float4*)As)[abase + la[mt] + ks * 32];
                split1(ar.x, ah[mt].x, al[mt].x);
                split1(ar.y, ah[mt].y, al[mt].y);
                split1(ar.z, ah[mt].z, al[mt].z);
                split1(ar.w, ah[mt].w, al[mt].w);
            }
#pragma unroll
            for (int nt = 0; nt < 4; nt++) {
                float2 br = ((const float2*)Bs)[bbase + lb[nt] + ks * 32];
                split1(br.x, bh[nt].x, bl[nt].x);
                split1(br.y, bh[nt].y, bl[nt].y);
            }
#pragma unroll
            for (int mt = 0; mt < 2; mt++)
#pragma unroll
                for (int nt = 0; nt < 4; nt++) {
                    float* a4 = acc[mt][nt];
                    MMA_TF32(a4[0], a4[1], a4[2], a4[3],
                             ah[mt].x, ah[mt].y, ah[mt].z, ah[mt].w, bl[nt].x, bl[nt].y);
                    MMA_TF32(a4[0], a4[1], a4[2], a4[3],
                             al[mt].x, al[mt].y, al[mt].z, al[mt].w, bh[nt].x, bh[nt].y);
                    MMA_TF32(a4[0], a4[1], a4[2], a4[3],
                             ah[mt].x, ah[mt].y, ah[mt].z, ah[mt].w, bh[nt].x, bh[nt].y);
                }
        }
        __syncthreads();
    }

    const int g = lane >> 2, t = lane & 3;
#pragma unroll
    for (int mt = 0; mt < 2; mt++) {
        int r0 = bm + wm * 32 + mt * 16 + g;
#pragma unroll
        for (int nt = 0; nt < 4; nt++) {
            int c0 = bn + wn * 32 + nt * 8 + t * 2;
            float vv[4] = {acc[mt][nt][0] * alpha, acc[mt][nt][1] * alpha,
                           acc[mt][nt][2] * alpha, acc[mt][nt][3] * alpha};
            if (act) {
#pragma unroll
                for (int q = 0; q < 4; q++) {
                    float v = vv[q];
                    float th = tanhf(0.7978845608028654f * (v + 0.044715f * v * v * v));
                    vv[q] = 0.5f * v * (1.f + th);
                }
            }
            if (R) {
                float2 r0v = *(const float2*)(R + (long long)r0 * ldr + c0);
                float2 r1v = *(const float2*)(R + (long long)(r0 + 8) * ldr + c0);
                vv[0] += r0v.x; vv[1] += r0v.y; vv[2] += r1v.x; vv[3] += r1v.y;
            }
            *(float2*)(C + (long long)r0 * ldc + c0) = make_float2(vv[0], vv[1]);
            *(float2*)(C + (long long)(r0 + 8) * ldc + c0) = make_float2(vv[2], vv[3]);
        }
    }
}

// ---------------- fallback SIMT NT gemm (router: N=9) ----------------
__global__ void gemm_nt(const float* __restrict__ A, const float* __restrict__ B,
                        float* __restrict__ C,
                        int M, int N, int K, int lda, int ldb, int ldc)
{
    int bm = blockIdx.y * 64, bn = blockIdx.x * 64;
    __shared__ float As[16][65], Bs[16][65];
    int tid = threadIdx.x;
    int tr = tid >> 4, tc = tid & 15;
    float acc[4][4] = {};
    for (int k0 = 0; k0 < K; k0 += 16) {
        for (int i = tid; i < 64 * 16; i += 256) {
            int m = i >> 4, k = i & 15;
            float v = 0.f;
            if (bm + m < M && k0 + k < K) v = A[(long long)(bm + m) * lda + k0 + k];
            As[k][m] = v;
        }
        for (int i = tid; i < 64 * 16; i += 256) {
            int n = i >> 4, k = i & 15;
            float v = 0.f;
            if (bn + n < N && k0 + k < K) v = B[(long long)(bn + n) * ldb + k0 + k];
            Bs[k][n] = v;
        }
        __syncthreads();
#pragma unroll
        for (int k = 0; k < 16; k++) {
            float a[4], b[4];
#pragma unroll
            for (int i = 0; i < 4; i++) a[i] = As[k][tr * 4 + i];
#pragma unroll
            for (int j = 0; j < 4; j++) b[j] = Bs[k][tc * 4 + j];
#pragma unroll
            for (int i = 0; i < 4; i++)
#pragma unroll
                for (int j = 0; j < 4; j++) acc[i][j] += a[i] * b[j];
        }
        __syncthreads();
    }
#pragma unroll
    for (int i = 0; i < 4; i++) {
        int m = bm + tr * 4 + i; if (m >= M) continue;
#pragma unroll
        for (int j = 0; j < 4; j++) {
            int n = bn + tc * 4 + j; if (n >= N) continue;
            C[(long long)m * ldc + n] = acc[i][j];
        }
    }
}

// ---------------- elementwise / reduction kernels ----------------
__global__ void embed_kernel(const int* __restrict__ ids, const float* __restrict__ ew)
{
    int idx = blockIdx.x * blockDim.x + threadIdx.x;
    if (idx < Tn * Dn) {
        int t = idx / Dn, d = idx % Dn;
        d_h[idx] = ew[(long long)ids[t] * Dn + d];
    }
}

__global__ void rope_table_kernel()
{
    int t = blockIdx.x; int i = threadIdx.x;                   // i in [0,32)
    double inv = pow(10000.0, -(2.0 * i) / 64.0);
    double f = (double)t * inv;
    float c = (float)cos(f), s = (float)sin(f);
    d_cos[t * DHn + i] = c; d_cos[t * DHn + i + 32] = c;
    d_sin[t * DHn + i] = s; d_sin[t * DHn + i + 32] = s;
}

__global__ void rmsnorm_kernel(const float* __restrict__ x, float* __restrict__ out,
                               const float* __restrict__ s)
{
    int r = blockIdx.x;
    const float* xr = x + (long long)r * Dn;
    float* orow = out + (long long)r * Dn;
    int tid = threadIdx.x;
    float ss = 0.f;
    for (int d = tid; d < Dn; d += 256) { float v = xr[d]; ss += v * v; }
    __shared__ float red[256];
    red[tid] = ss; __syncthreads();
    for (int st = 128; st > 0; st >>= 1) { if (tid < st) red[tid] += red[tid + st]; __syncthreads(); }
    float inv = rsqrtf(red[0] / Dn + 1e-6f);
    for (int d = tid; d < Dn; d += 256) orow[d] = xr[d] * inv * s[d];
}

// fused dispatch: gather h[slot] once -> write residual copy (xin) AND normalized
// expert input (eu, ordered [attn0..3 | ffn0..3]). Empty slots produce zero rows,
// matching the reference. Same per-row summation order as rmsnorm_kernel.
__global__ void gather_rmsnorm_kernel(const float* __restrict__ attn_ln,
                                      const float* __restrict__ ffn_ln)
{
    int c = blockIdx.x, e = blockIdx.y;
    int tok = d_slot[e * CAPn + c];
    const float* sr = (e & 1) ? ffn_ln + ((e - 1) >> 1) * Dn : attn_ln + (e >> 1) * Dn;
    int eidx = (e & 1) ? 4 + (e >> 1) : (e >> 1);
    float* xrow = d_xin + ((long long)e * CAPn + c) * Dn;
    float* erow = d_eu + ((long long)eidx * CAPn + c) * Dn;
    int tid = threadIdx.x;
    float v0 = 0.f, v1 = 0.f;
    if (tok >= 0) {
        v0 = d_h[(long long)tok * Dn + tid];
        v1 = d_h[(long long)tok * Dn + tid + 256];
    }
    __shared__ float red[256];
    red[tid] = v0 * v0 + v1 * v1;
    __syncthreads();
    for (int st = 128; st > 0; st >>= 1) { if (tid < st) red[tid] += red[tid + st]; __syncthreads(); }
    float inv = rsqrtf(red[0] / Dn + 1e-6f);
    xrow[tid] = v0; xrow[tid + 256] = v1;
    erow[tid] = v0 * inv * sr[tid];
    erow[tid + 256] = v1 * inv * sr[tid + 256];
}

// slot==nullptr: token id == row (backbone). Else gather cos/sin via slot[b*sstride + r];
// empty slots (tok<0) use cos=sin=0, matching the reference's zero-gathered rows.
__global__ void rope_apply_kernel(float* __restrict__ qkv, long long qbs,
                                  const int* __restrict__ slot, int sstride)
{
    int r = blockIdx.x, b = blockIdx.y;
    float* base = qkv + b * qbs + (long long)r * (3 * Dn);
    int tok = slot ? slot[b * sstride + r] : r;
    int hh = threadIdx.x >> 5, i = threadIdx.x & 31;
    float c = 0.f, s = 0.f;
    if (tok >= 0) { c = d_cos[tok * DHn + i]; s = d_sin[tok * DHn + i]; }
    float* q = base + hh * DHn;
    float x1 = q[i], x2 = q[i + 32];
    q[i] = x1 * c - x2 * s;
    q[i + 32] = x2 * c + x1 * s;
    float* k = base + Dn + hh * DHn;
    x1 = k[i]; x2 = k[i + 32];
    k[i] = x1 * c - x2 * s;
    k[i + 32] = x2 * c + x1 * s;
}

// causal softmax, single global pass; row cached in registers. Zero-fills to next
// 128 boundary (all the causal-aware AV GEMM ever reads).
__global__ void softmax_causal(float* __restrict__ sc, int C)
{
    int r = blockIdx.x; long long b = blockIdx.y;
    float* row = sc + b * (long long)C * C + (long long)r * C;
    int tid = threadIdx.x;
    __shared__ float red[256];
    float v[8];
    float mx = -3.4e38f;
#pragma unroll
    for (int k = 0; k < 8; k++) {
        int j = tid + (k << 8);
        if (j < C && j <= r) { v[k] = row[j]; mx = fmaxf(mx, v[k]); }
    }
    red[tid] = mx; __syncthreads();
    for (int st = 128; st > 0; st >>= 1) { if (tid < st) red[tid] = fmaxf(red[tid], red[tid + st]); __syncthreads(); }
    mx = red[0]; __syncthreads();
    float sum = 0.f;
#pragma unroll
    for (int k = 0; k < 8; k++) {
        int j = tid + (k << 8);
        if (j < C && j <= r) { float e = expf(v[k] - mx); v[k] = e; sum += e; }
    }
    red[tid] = sum; __syncthreads();
    for (int st = 128; st > 0; st >>= 1) { if (tid < st) red[tid] += red[tid + st]; __syncthreads(); }
    float inv = 1.f / red[0];
    int lim = ((r >> 7) + 1) << 7;
#pragma unroll
    for (int k = 0; k < 8; k++) {
        int j = tid + (k << 8);
        if (j < lim) row[j] = (j <= r) ? v[k] * inv : 0.f;
    }
}

__global__ void router_post_kernel()
{
    int t = blockIdx.x * blockDim.x + threadIdx.x;
    if (t >= Tn) return;
    float lg[9];
#pragma unroll
    for (int e = 0; e < 9; e++) lg[e] = d_logits[t * 9 + e];
    int i1 = 0;
#pragma unroll
    for (int e = 1; e < 9; e++) if (lg[e] > lg[i1]) i1 = e;
    int i2 = -1;
#pragma unroll
    for (int e = 0; e < 9; e++) { if (e == i1) continue; if (i2 < 0 || lg[e] > lg[i2]) i2 = e; }
    float mx = lg[i1];
    float p[9]; float sum = 0.f;
#pragma unroll
    for (int e = 0; e < 9; e++) { p[e] = expf(lg[e] - mx); sum += p[e]; }
    float inv = 1.f / sum;
#pragma unroll
    for (int e = 0; e < NEn; e++) {
        float pe = p[e] * inv;
        d_probs8[t * NEn + e] = pe;
        bool m = (e == i1) || (e == i2);
        d_g[e * Tn + t] = m ? pe : -INFINITY;
    }
}

// exact jax.lax.top_k order via rank-by-comparison; gate vector tiled through smem.
__global__ void rank_kernel()
{
    int e = blockIdx.y;
    int t = blockIdx.x * 256 + threadIdx.x;
    float gt = d_g[e * Tn + t];
    __shared__ float gs[256];
    int rank = 0;
    for (int j0 = 0; j0 < Tn; j0 += 256) {
        gs[threadIdx.x] = d_g[e * Tn + j0 + threadIdx.x];
        __syncthreads();
#pragma unroll 8
        for (int jj = 0; jj < 256; jj++) {
            float gj = gs[jj];
            rank += (gj > gt) || (gj == gt && (j0 + jj) < t);
        }
        __syncthreads();
    }
    bool msk = !isinf(gt);
    if (rank < CAPn) d_slot[e * CAPn + rank] = msk ? t : -1;
    d_cof[e * Tn + t] = (rank < CAPn && msk) ? rank : -1;
}

__global__ void combine_kernel()
{
    int idx = blockIdx.x * blockDim.x + threadIdx.x;
    if (idx >= Tn * Dn) return;
    int t = idx / Dn, d = idx % Dn;
    float acc = 0.f, rho = 0.f;
#pragma unroll
    for (int e = 0; e < NEn; e++) {
        int c = d_cof[e * Tn + t];
        if (c >= 0) {
            float w = d_probs8[t * NEn + e];
            rho += w;
            acc += w * d_exout[((long long)e * CAPn + c) * Dn + d];
        }
    }
    float hv = d_h[idx];
    d_h[idx] = hv + acc - rho * hv;
}

// ---------------- host orchestration ----------------
static cudaStream_t g_s2 = nullptr;       // side stream for FFN branch (fork-join)
static cudaEvent_t  g_ev_fork = nullptr, g_ev_join = nullptr;

extern "C" void kernel_launch(void* const* d_in, const int* in_sizes, int n_in,
                              void* d_out, int out_size)
{
    (void)in_sizes; (void)n_in; (void)out_size;
    const int*   ids      = (const int*)d_in[0];
    const float* embed_w  = (const float*)d_in[1];
    const float* router_w = (const float*)d_in[2];
    const float* attn_qkv = (const float*)d_in[3];
    const float* attn_o   = (const float*)d_in[4];
    const float* attn_ln  = (const float*)d_in[5];
    const float* ffn_w1   = (const float*)d_in[6];
    const float* ffn_w2   = (const float*)d_in[7];
    const float* ffn_ln   = (const float*)d_in[8];
    const float* bb_qkv   = (const float*)d_in[9];
    const float* bb_o     = (const float*)d_in[10];
    const float* bb_ln    = (const float*)d_in[11];
    const float* lnout_s  = (const float*)d_in[12];
    float* out = (float*)d_out;

    if (!g_s2) {
        cudaStreamCreateWithFlags(&g_s2, cudaStreamNonBlocking);
        cudaEventCreateWithFlags(&g_ev_fork, cudaEventDisableTiming);
        cudaEventCreateWithFlags(&g_ev_join, cudaEventDisableTiming);
    }

    float *h, *u, *qkv, *att, *sc, *logits, *eu, *eqkv, *eatt, *ffh, *exout, *xin;
    int* slot;
    cudaGetSymbolAddress((void**)&h, d_h);
    cudaGetSymbolAddress((void**)&u, d_u);
    cudaGetSymbolAddress((void**)&qkv, d_qkv);
    cudaGetSymbolAddress((void**)&att, d_att);
    cudaGetSymbolAddress((void**)&sc, d_sc);
    cudaGetSymbolAddress((void**)&logits, d_logits);
    cudaGetSymbolAddress((void**)&eu, d_eu);
    cudaGetSymbolAddress((void**)&eqkv, d_eqkv);
    cudaGetSymbolAddress((void**)&eatt, d_eatt);
    cudaGetSymbolAddress((void**)&ffh, d_ffh);
    cudaGetSymbolAddress((void**)&exout, d_exout);
    cudaGetSymbolAddress((void**)&xin, d_xin);
    cudaGetSymbolAddress((void**)&slot, d_slot);

    auto NT = [](const float* A, const float* B, float* C, const float* R,
                 int M, int N, int K, int lda, int ldb, int ldc, int ldr,
                 long long sA, long long sB, long long sC, long long sR, int nb,
                 float alpha, int act, int causal, cudaStream_t st) {
        dim3 g(N / 64, M / 128, nb);
        gemm_tf32x3<true><<<g, 256, 0, st>>>(A, B, C, R, M, N, K, lda, ldb, ldc, ldr,
                                             sA, sB, sC, sR, alpha, act, causal, 0, 0, 0, 0);
    };
    auto NN = [](const float* A, const float* B, float* C,
                 int M, int N, int K, int lda, int ldb, int ldc,
                 long long sA, long long sB, long long sC, int nb, int causal) {
        dim3 g(N / 64, M / 128, nb);
        gemm_tf32x3<false><<<g, 256>>>(A, B, C, nullptr, M, N, K, lda, ldb, ldc, 0,
                                       sA, sB, sC, 0, 1.f, 0, causal, 0, 0, 0, 0);
    };

    // ---- backbone ----
    embed_kernel<<<(Tn * Dn + 255) / 256, 256>>>(ids, embed_w);
    rope_table_kernel<<<Tn, 32>>>();
    rmsnorm_kernel<<<Tn, 256>>>(h, u, bb_ln);
    NT(u, bb_qkv, qkv, nullptr, Tn, 3 * Dn, Dn, Dn, Dn, 3 * Dn, 0, 0, 0, 0, 0, 1, 1.f, 0, 0, 0);
    rope_apply_kernel<<<dim3(Tn, 1), 256>>>(qkv, 0, nullptr, 0);
    NT(qkv, qkv + Dn, sc, nullptr, Tn, Tn, DHn, 3 * Dn, 3 * Dn, Tn, 0,
       64, 64, (long long)Tn * Tn, 0, NHn, 0.125f, 0, 1, 0);
    softmax_causal<<<dim3(Tn, NHn), 256>>>(sc, Tn);
    NN(sc, qkv + 2 * Dn, att, Tn, DHn, Tn, Tn, 3 * Dn, Dn,
       (long long)Tn * Tn, 64, 64, NHn, 1);
    NT(att, bb_o, h, h, Tn, Dn, Dn, Dn, Dn, Dn, Dn, 0, 0, 0, 0, 1, 1.f, 0, 0, 0);

    // ---- hops ----
    for (int hop = 0; hop < 2; hop++) {
        {   // router logits (N=9): SIMT fp32 path
            dim3 g(1, (Tn + 63) / 64, 1);
            gemm_nt<<<g, 256>>>(h, router_w + hop * 9 * Dn, logits,
                                Tn, 9, Dn, Dn, Dn, 9);
        }
        router_post_kernel<<<(Tn + 255) / 256, 256>>>();
        rank_kernel<<<dim3(Tn / 256, NEn), 256>>>();
        gather_rmsnorm_kernel<<<dim3(CAPn, NEn), 256>>>(attn_ln, ffn_ln);

        // ---- fork: FFN chain on side stream (independent of attention chain) ----
        cudaEventRecord(g_ev_fork, 0);
        cudaStreamWaitEvent(g_s2, g_ev_fork, 0);

        // FFN experts on g_s2 (eu batches [4..8)), gelu fused into w1 GEMM
        NT(eu + 4LL * CAPn * Dn, ffn_w1, ffh, nullptr, CAPn, 4 * Dn, Dn, Dn, Dn, 4 * Dn, 0,
           (long long)CAPn * Dn, 4LL * Dn * Dn, (long long)CAPn * 4 * Dn, 0, 4, 1.f, 1, 0, g_s2);
        NT(ffh, ffn_w2, exout + CAPn * Dn, xin + CAPn * Dn, CAPn, Dn, 4 * Dn,
           4 * Dn, 4 * Dn, Dn, Dn,
           (long long)CAPn * 4 * Dn, 4LL * Dn * Dn, 2LL * CAPn * Dn, 2LL * CAPn * Dn, 4,
           1.f, 0, 0, g_s2);

        // Attention experts on default stream (eu batches [0..4))
        NT(eu, attn_qkv, eqkv, nullptr, CAPn, 3 * Dn, Dn, Dn, Dn, 3 * Dn, 0,
           (long long)CAPn * Dn, 3LL * Dn * Dn, (long long)CAPn * 3 * Dn, 0, 4, 1.f, 0, 0, 0);
        rope_apply_kernel<<<dim3(CAPn, 4), 256>>>(eqkv, (long long)CAPn * 3 * Dn,
                                                  slot, 2 * CAPn);
        {   // merged scores: z = j*8 + head
            dim3 g(CAPn / 64, CAPn / 128, 32);
            gemm_tf32x3<true><<<g, 256>>>(eqkv, eqkv + Dn, sc, nullptr,
                CAPn, CAPn, DHn, 3 * Dn, 3 * Dn, CAPn, 0,
                64, 64, (long long)CAPn * CAPn, 0, 0.125f, 0, 1,
                1, 3LL * CAPn * Dn, 3LL * CAPn * Dn, 8LL * CAPn * CAPn);
        }
        softmax_causal<<<dim3(CAPn, 4 * NHn), 256>>>(sc, CAPn);
        {   // merged AV: z = j*8 + head
            dim3 g(DHn / 64, CAPn / 128, 32);
            gemm_tf32x3<false><<<g, 256>>>(sc, eqkv + 2 * Dn, eatt, nullptr,
                CAPn, DHn, CAPn, CAPn, 3 * Dn, Dn, 0,
                (long long)CAPn * CAPn, 64, 64, 0, 1.f, 0, 1,
                1, 8LL * CAPn * CAPn, 3LL * CAPn * Dn, (long long)CAPn * Dn);
        }
        NT(eatt, attn_o, exout, xin, CAPn, Dn, Dn, Dn, Dn, Dn, Dn,
           (long long)CAPn * Dn, (long long)Dn * Dn, 2LL * CAPn * Dn, 2LL * CAPn * Dn, 4,
           1.f, 0, 0, 0);

        // ---- join: default stream waits for FFN branch ----
        cudaEventRecord(g_ev_join, g_s2);
        cudaStreamWaitEvent(0, g_ev_join, 0);

        combine_kernel<<<(Tn * Dn + 255) / 256, 256>>>();
    }

    // ---- final rmsnorm -> output ----
    rmsnorm_kernel<<<Tn, 256>>>(h, out, lnout_s);
}

// round 17
// speedup vs baseline: 1.1446x; 1.0145x over previous
#include <cuda_runtime.h>
#include <math.h>
#include <stdint.h>

namespace {
constexpr int Tn  = 2048;
constexpr int Dn  = 512;
constexpr int NHn = 8;
constexpr int DHn = 64;
constexpr int CAPn = 512;
constexpr int NEn = 8;
}

// ---------------- scratch (static device globals; no runtime allocation) ----------------
__device__ float d_h[Tn * Dn];
__device__ float d_u[Tn * Dn];
__device__ float d_qkv[Tn * 3 * Dn];
__device__ float d_att[Tn * Dn];
__device__ float d_cos[Tn * DHn];
__device__ float d_sin[Tn * DHn];
__device__ float d_sc[(size_t)NHn * Tn * Tn];
__device__ float d_logits[Tn * 9];
__device__ float d_probs8[Tn * NEn];
__device__ float d_g[NEn * Tn];
__device__ int   d_cof[NEn * Tn];
__device__ int   d_slot[NEn * CAPn];
__device__ float d_xin[NEn * CAPn * Dn];
__device__ float d_eu[NEn * CAPn * Dn];          // [attn0..3 | ffn0..3] normalized inputs
__device__ float d_eqkv[4 * CAPn * 3 * Dn];
__device__ float d_eatt[4 * CAPn * Dn];
__device__ float d_ffh[4 * CAPn * 4 * Dn];
__device__ float d_exout[NEn * CAPn * Dn];

// ======================= TF32x3 tensor-core GEMM (fp32-accurate) =======================
// 128x64 CTA tile, 256 threads (8 warps of 32x32) — measured-optimal config.
// C[M,N] = act( alpha * A * op(B) ) (+R).  A: row-major MxK (lda).
// BNT=true : B row-major NxK (ldb)  -> C = A * B^T
// BNT=false: B row-major KxN (ldb)  -> C = A * B
// causal (NT): skip output tiles fully above the diagonal (bn >= bm+128).
// causal (NN): clamp K to bm+128 (A columns beyond hold exact zeros).
// zsplit: batch index decomposes as z = zhi*8 + zlo with strides (s?2, s?1).
__device__ __forceinline__ uint32_t f2tf32(float x) {
    uint32_t r; asm("cvt.rna.tf32.f32 %0, %1;" : "=r"(r) : "f"(x)); return r;
}
// hi: RNA-rounded tf32. lo: residual passed RAW — tensor core reads .tf32 operands
// as the top 19 bits (implicit RZ truncation); truncation error <= 2^-25 |v|.
__device__ __forceinline__ void split1(float v, uint32_t& hi, uint32_t& lo) {
    hi = f2tf32(v);
    lo = __float_as_uint(v - __uint_as_float(hi));
}
// cyclic rotate-left so that position j holds element (j+r)&3
__device__ __forceinline__ float4 rotl4(float4 t, int r) {
    if (r & 1) t = make_float4(t.y, t.z, t.w, t.x);
    if (r & 2) t = make_float4(t.z, t.w, t.x, t.y);
    return t;
}
__device__ __forceinline__ int4 rotl4(int4 t, int r) {
    if (r & 1) t = make_int4(t.y, t.z, t.w, t.x);
    if (r & 2) t = make_int4(t.z, t.w, t.x, t.y);
    return t;
}

#define MMA_TF32(c0,c1,c2,c3,a0,a1,a2,a3,b0,b1)                                  \
    asm volatile("mma.sync.aligned.m16n8k8.row.col.f32.tf32.tf32.f32 "           \
                 "{%0,%1,%2,%3}, {%4,%5,%6,%7}, {%8,%9}, {%0,%1,%2,%3};"         \
                 : "+f"(c0), "+f"(c1), "+f"(c2), "+f"(c3)                         \
                 : "r"(a0), "r"(a1), "r"(a2), "r"(a3), "r"(b0), "r"(b1))

template<bool BNT>
__global__ void __launch_bounds__(256, 2)
gemm_tf32x3(const float* __restrict__ A, const float* __restrict__ B,
            float* __restrict__ C, const float* __restrict__ R,
            int M, int N, int K, int lda, int ldb, int ldc, int ldr,
            long long sA, long long sB, long long sC, long long sR,
            float alpha, int act, int causal,
            int zsplit, long long sA2, long long sB2, long long sC2)
{
    __shared__ float4 As[2][1024];
    __shared__ float2 Bs[2][1024];
    float* asw = (float*)As;
    float* bsw = (float*)Bs;

    int z = blockIdx.z;
    if (zsplit) {
        int zh = z >> 3, zl = z & 7;
        A += zh * sA2 + zl * sA;
        B += zh * sB2 + zl * sB;
        C += zh * sC2 + zl * sC;
    } else {
        A += z * sA; B += z * sB; C += z * sC; if (R) R += z * sR;
    }
    const int bm = blockIdx.y * 128, bn = blockIdx.x * 64;
    if (BNT && causal && bn >= bm + 128) return;     // fully-masked causal tile
    const int tid = threadIdx.x;
    const int warp = tid >> 5, lane = tid & 31;
    const int wm = warp >> 1, wn = warp & 1;          // 4 warps in M, 2 in N

    const int rA = ((lane >> 1) & 3) ^ (((lane >> 4) & 1) << 1);
    const int rB = BNT ? ((lane >> 1) & 3)
                       : (((lane >> 1) & 3) ^ ((lane >> 3) & 1));
    const int4 oA = rotl4(make_int4(0, 4, 8, 12), rA);
    const int4 oB = BNT ? rotl4(make_int4(0, 2, 4, 6), rB)
                        : rotl4(make_int4(0, 8, 16, 24), rB);

    const float* gA[4];
#pragma unroll
    for (int i = 0; i < 4; i++) {
        int idx = tid + i * 256;
        int m = idx >> 3, k = (idx & 7) * 4;
        gA[i] = A + (long long)(bm + m) * lda + k;
    }
    const float* gB[2];
#pragma unroll
    for (int i = 0; i < 2; i++) {
        int idx = tid + i * 256;
        if (BNT) { int n = idx >> 3, k = (idx & 7) * 4; gB[i] = B + (long long)(bn + n) * ldb + k; }
        else     { int k = idx >> 4, n = (idx & 15) * 4; gB[i] = B + (long long)k * ldb + bn + n; }
    }
    const long long gBstep = BNT ? 32 : 32LL * ldb;

    int wa[4];
#pragma unroll
    for (int i = 0; i < 4; i++) {
        int idx = tid + i * 256;
        int m = idx >> 3, kb = (idx & 7) * 4;
        int mt = m >> 4, ks = kb >> 3, mm = m & 15;
        int ln = (mm & 7) * 4;
        int rg = (mm >> 3) + 2 * ((kb & 7) >> 2);
        wa[i] = ((mt * 4 + ks) * 32 + ln) * 4 + rg;
    }
    int wb[2];
#pragma unroll
    for (int i = 0; i < 2; i++) {
        int idx = tid + i * 256;
        if (BNT) {
            int n = idx >> 3, kb = (idx & 7) * 4;
            int nt = n >> 3, ks = kb >> 3;
            int ln = (n & 7) * 4;
            int rg = (kb & 7) >> 2;
            wb[i] = ((nt * 4 + ks) * 32 + ln) * 2 + rg;
        } else {
            int k = idx >> 4, nb = (idx & 15) * 4;
            int nt = nb >> 3, ks = k >> 3;
            int ln = (nb & 7) * 4 + (k & 3);
            int rg = (k & 7) >> 2;
            wb[i] = ((nt * 4 + ks) * 32 + ln) * 2 + rg;
        }
    }

    int la[2], lb[4];
#pragma unroll
    for (int mt = 0; mt < 2; mt++) la[mt] = ((wm * 2 + mt) * 4) * 32 + lane;
#pragma unroll
    for (int nt = 0; nt < 4; nt++) lb[nt] = ((wn * 4 + nt) * 4) * 32 + lane;

    float4 pa[4];
    float4 pb[2];

    auto gload = [&]() {
#pragma unroll
        for (int i = 0; i < 4; i++) { pa[i] = *(const float4*)gA[i]; gA[i] += 32; }
#pragma unroll
        for (int i = 0; i < 2; i++) { pb[i] = *(const float4*)gB[i]; gB[i] += gBstep; }
    };
    auto sts = [&](int buf) {
        int ab = buf << 12;
        int bb = buf << 11;
#pragma unroll
        for (int i = 0; i < 4; i++) {
            float4 t = rotl4(pa[i], rA);
            int base = ab + wa[i];
            asw[base + oA.x] = t.x;
            asw[base + oA.y] = t.y;
            asw[base + oA.z] = t.z;
            asw[base + oA.w] = t.w;
        }
#pragma unroll
        for (int i = 0; i < 2; i++) {
            float4 t = rotl4(pb[i], rB);
            int base = bb + wb[i];
            bsw[base + oB.x] = t.x;
            bsw[base + oB.y] = t.y;
            bsw[base + oB.z] = t.z;
            bsw[base + oB.w] = t.w;
        }
    };

    float acc[2][4][4] = {};
    const int Keff = (!BNT && causal) ? (bm + 128 < K ? bm + 128 : K) : K;
    const int nc = Keff >> 5;

    gload();
    sts(0);
    if (nc > 1) gload();
    __syncthreads();

    for (int c = 0; c < nc; c++) {
        if (c + 1 < nc) sts((c + 1) & 1);
        if (c + 2 < nc) gload();
        int buf = c & 1;
        int abase = buf << 10;
        int bbase = buf << 10;
#pragma unroll
        for (int ks = 0; ks < 4; ks++) {
            uint4 ah[2], al[2]; uint2 bh[4], bl[4];
#pragma unroll
            for (int mt = 0; mt < 2; mt++) {
                float4 ar = ((const float4*)As)[abase + la[mt] + ks * 32];
                split1(ar.x, ah[mt].x, al[mt].x);
                split1(ar.y, ah[mt].y, al[mt].y);
                split1(ar.z, ah[mt].z, al[mt].z);
                split1(ar.w, ah[mt].w, al[mt].w);
            }
#pragma unroll
            for (int nt = 0; nt < 4; nt++) {
                float2 br = ((const float2*)Bs)[bbase + lb[nt] + ks * 32];
                split1(br.x, bh[nt].x, bl[nt].x);
                split1(br.y, bh[nt].y, bl[nt].y);
            }
#pragma unroll
            for (int mt = 0; mt < 2; mt++)
#pragma unroll
                for (int nt = 0; nt < 4; nt++) {
                    float* a4 = acc[mt][nt];
                    MMA_TF32(a4[0], a4[1], a4[2], a4[3],
                             ah[mt].x, ah[mt].y, ah[mt].z, ah[mt].w, bl[nt].x, bl[nt].y);
                    MMA_TF32(a4[0], a4[1], a4[2], a4[3],
                             al[mt].x, al[mt].y, al[mt].z, al[mt].w, bh[nt].x, bh[nt].y);
                    MMA_TF32(a4[0], a4[1], a4[2], a4[3],
                             ah[mt].x, ah[mt].y, ah[mt].z, ah[mt].w, bh[nt].x, bh[nt].y);
                }
        }
        __syncthreads();
    }

    const int g = lane >> 2, t = lane & 3;
#pragma unroll
    for (int mt = 0; mt < 2; mt++) {
        int r0 = bm + wm * 32 + mt * 16 + g;
#pragma unroll
        for (int nt = 0; nt < 4; nt++) {
            int c0 = bn + wn * 32 + nt * 8 + t * 2;
            float vv[4] = {acc[mt][nt][0] * alpha, acc[mt][nt][1] * alpha,
                           acc[mt][nt][2] * alpha, acc[mt][nt][3] * alpha};
            if (act) {
#pragma unroll
                for (int q = 0; q < 4; q++) {
                    float v = vv[q];
                    float th = tanhf(0.7978845608028654f * (v + 0.044715f * v * v * v));
                    vv[q] = 0.5f * v * (1.f + th);
                }
            }
            if (R) {
                float2 r0v = *(const float2*)(R + (long long)r0 * ldr + c0);
                float2 r1v = *(const float2*)(R + (long long)(r0 + 8) * ldr + c0);
                vv[0] += r0v.x; vv[1] += r0v.y; vv[2] += r1v.x; vv[3] += r1v.y;
            }
            *(float2*)(C + (long long)r0 * ldc + c0) = make_float2(vv[0], vv[1]);
            *(float2*)(C + (long long)(r0 + 8) * ldc + c0) = make_float2(vv[2], vv[3]);
        }
    }
}

// ---------------- fallback SIMT NT gemm (router: N=9) ----------------
__global__ void gemm_nt(const float* __restrict__ A, const float* __restrict__ B,
                        float* __restrict__ C,
                        int M, int N, int K, int lda, int ldb, int ldc)
{
    int bm = blockIdx.y * 64, bn = blockIdx.x * 64;
    __shared__ float As[16][65], Bs[16][65];
    int tid = threadIdx.x;
    int tr = tid >> 4, tc = tid & 15;
    float acc[4][4] = {};
    for (int k0 = 0; k0 < K; k0 += 16) {
        for (int i = tid; i < 64 * 16; i += 256) {
            int m = i >> 4, k = i & 15;
            float v = 0.f;
            if (bm + m < M && k0 + k < K) v = A[(long long)(bm + m) * lda + k0 + k];
            As[k][m] = v;
        }
        for (int i = tid; i < 64 * 16; i += 256) {
            int n = i >> 4, k = i & 15;
            float v = 0.f;
            if (bn + n < N && k0 + k < K) v = B[(long long)(bn + n) * ldb + k0 + k];
            Bs[k][n] = v;
        }
        __syncthreads();
#pragma unroll
        for (int k = 0; k < 16; k++) {
            float a[4], b[4];
#pragma unroll
            for (int i = 0; i < 4; i++) a[i] = As[k][tr * 4 + i];
#pragma unroll
            for (int j = 0; j < 4; j++) b[j] = Bs[k][tc * 4 + j];
#pragma unroll
            for (int i = 0; i < 4; i++)
#pragma unroll
                for (int j = 0; j < 4; j++) acc[i][j] += a[i] * b[j];
        }
        __syncthreads();
    }
#pragma unroll
    for (int i = 0; i < 4; i++) {
        int m = bm + tr * 4 + i; if (m >= M) continue;
#pragma unroll
        for (int j = 0; j < 4; j++) {
            int n = bn + tc * 4 + j; if (n >= N) continue;
            C[(long long)m * ldc + n] = acc[i][j];
        }
    }
}

// ---------------- elementwise / reduction kernels ----------------
__global__ void embed_kernel(const int* __restrict__ ids, const float* __restrict__ ew)
{
    int idx = blockIdx.x * blockDim.x + threadIdx.x;
    if (idx < Tn * Dn) {
        int t = idx / Dn, d = idx % Dn;
        d_h[idx] = ew[(long long)ids[t] * Dn + d];
    }
}

__global__ void rope_table_kernel()
{
    int t = blockIdx.x; int i = threadIdx.x;                   // i in [0,32)
    double inv = pow(10000.0, -(2.0 * i) / 64.0);
    double f = (double)t * inv;
    float c = (float)cos(f), s = (float)sin(f);
    d_cos[t * DHn + i] = c; d_cos[t * DHn + i + 32] = c;
    d_sin[t * DHn + i] = s; d_sin[t * DHn + i + 32] = s;
}

__global__ void rmsnorm_kernel(const float* __restrict__ x, float* __restrict__ out,
                               const float* __restrict__ s)
{
    int r = blockIdx.x;
    const float* xr = x + (long long)r * Dn;
    float* orow = out + (long long)r * Dn;
    int tid = threadIdx.x;
    float ss = 0.f;
    for (int d = tid; d < Dn; d += 256) { float v = xr[d]; ss += v * v; }
    __shared__ float red[256];
    red[tid] = ss; __syncthreads();
    for (int st = 128; st > 0; st >>= 1) { if (tid < st) red[tid] += red[tid + st]; __syncthreads(); }
    float inv = rsqrtf(red[0] / Dn + 1e-6f);
    for (int d = tid; d < Dn; d += 256) orow[d] = xr[d] * inv * s[d];
}

// fused dispatch: gather h[slot] once -> write residual copy (xin) AND normalized
// expert input (eu, ordered [attn0..3 | ffn0..3]). Empty slots produce zero rows,
// matching the reference. Same per-row summation order as rmsnorm_kernel.
__global__ void gather_rmsnorm_kernel(const float* __restrict__ attn_ln,
                                      const float* __restrict__ ffn_ln)
{
    int c = blockIdx.x, e = blockIdx.y;
    int tok = d_slot[e * CAPn + c];
    const float* sr = (e & 1) ? ffn_ln + ((e - 1) >> 1) * Dn : attn_ln + (e >> 1) * Dn;
    int eidx = (e & 1) ? 4 + (e >> 1) : (e >> 1);
    float* xrow = d_xin + ((long long)e * CAPn + c) * Dn;
    float* erow = d_eu + ((long long)eidx * CAPn + c) * Dn;
    int tid = threadIdx.x;
    float v0 = 0.f, v1 = 0.f;
    if (tok >= 0) {
        v0 = d_h[(long long)tok * Dn + tid];
        v1 = d_h[(long long)tok * Dn + tid + 256];
    }
    __shared__ float red[256];
    red[tid] = v0 * v0 + v1 * v1;
    __syncthreads();
    for (int st = 128; st > 0; st >>= 1) { if (tid < st) red[tid] += red[tid + st]; __syncthreads(); }
    float inv = rsqrtf(red[0] / Dn + 1e-6f);
    xrow[tid] = v0; xrow[tid + 256] = v1;
    erow[tid] = v0 * inv * sr[tid];
    erow[tid + 256] = v1 * inv * sr[tid + 256];
}

// slot==nullptr: token id == row (backbone). Else gather cos/sin via slot[b*sstride + r];
// empty slots (tok<0) use cos=sin=0, matching the reference's zero-gathered rows.
__global__ void rope_apply_kernel(float* __restrict__ qkv, long long qbs,
                                  const int* __restrict__ slot, int sstride)
{
    int r = blockIdx.x, b = blockIdx.y;
    float* base = qkv + b * qbs + (long long)r * (3 * Dn);
    int tok = slot ? slot[b * sstride + r] : r;
    int hh = threadIdx.x >> 5, i = threadIdx.x & 31;
    float c = 0.f, s = 0.f;
    if (tok >= 0) { c = d_cos[tok * DHn + i]; s = d_sin[tok * DHn + i]; }
    float* q = base + hh * DHn;
    float x1 = q[i], x2 = q[i + 32];
    q[i] = x1 * c - x2 * s;
    q[i + 32] = x2 * c + x1 * s;
    float* k = base + Dn + hh * DHn;
    x1 = k[i]; x2 = k[i + 32];
    k[i] = x1 * c - x2 * s;
    k[i + 32] = x2 * c + x1 * s;
}

// causal softmax, single global pass; row cached in registers. Zero-fills to next
// 128 boundary (all the causal-aware AV GEMM ever reads).
__global__ void softmax_causal(float* __restrict__ sc, int C)
{
    int r = blockIdx.x; long long b = blockIdx.y;
    float* row = sc + b * (long long)C * C + (long long)r * C;
    int tid = threadIdx.x;
    __shared__ float red[256];
    float v[8];
    float mx = -3.4e38f;
#pragma unroll
    for (int k = 0; k < 8; k++) {
        int j = tid + (k << 8);
        if (j < C && j <= r) { v[k] = row[j]; mx = fmaxf(mx, v[k]); }
    }
    red[tid] = mx; __syncthreads();
    for (int st = 128; st > 0; st >>= 1) { if (tid < st) red[tid] = fmaxf(red[tid], red[tid + st]); __syncthreads(); }
    mx = red[0]; __syncthreads();
    float sum = 0.f;
#pragma unroll
    for (int k = 0; k < 8; k++) {
        int j = tid + (k << 8);
        if (j < C && j <= r) { float e = expf(v[k] - mx); v[k] = e; sum += e; }
    }
    red[tid] = sum; __syncthreads();
    for (int st = 128; st > 0; st >>= 1) { if (tid < st) red[tid] += red[tid + st]; __syncthreads(); }
    float inv = 1.f / red[0];
    int lim = ((r >> 7) + 1) << 7;
#pragma unroll
    for (int k = 0; k < 8; k++) {
        int j = tid + (k << 8);
        if (j < lim) row[j] = (j <= r) ? v[k] * inv : 0.f;
    }
}

__global__ void router_post_kernel()
{
    int t = blockIdx.x * blockDim.x + threadIdx.x;
    if (t >= Tn) return;
    float lg[9];
#pragma unroll
    for (int e = 0; e < 9; e++) lg[e] = d_logits[t * 9 + e];
    int i1 = 0;
#pragma unroll
    for (int e = 1; e < 9; e++) if (lg[e] > lg[i1]) i1 = e;
    int i2 = -1;
#pragma unroll
    for (int e = 0; e < 9; e++) { if (e == i1) continue; if (i2 < 0 || lg[e] > lg[i2]) i2 = e; }
    float mx = lg[i1];
    float p[9]; float sum = 0.f;
#pragma unroll
    for (int e = 0; e < 9; e++) { p[e] = expf(lg[e] - mx); sum += p[e]; }
    float inv = 1.f / sum;
#pragma unroll
    for (int e = 0; e < NEn; e++) {
        float pe = p[e] * inv;
        d_probs8[t * NEn + e] = pe;
        bool m = (e == i1) || (e == i2);
        d_g[e * Tn + t] = m ? pe : -INFINITY;
    }
}

// exact jax.lax.top_k order via rank-by-comparison; gate vector tiled through smem.
__global__ void rank_kernel()
{
    int e = blockIdx.y;
    int t = blockIdx.x * 256 + threadIdx.x;
    float gt = d_g[e * Tn + t];
    __shared__ float gs[256];
    int rank = 0;
    for (int j0 = 0; j0 < Tn; j0 += 256) {
        gs[threadIdx.x] = d_g[e * Tn + j0 + threadIdx.x];
        __syncthreads();
#pragma unroll 8
        for (int jj = 0; jj < 256; jj++) {
            float gj = gs[jj];
            rank += (gj > gt) || (gj == gt && (j0 + jj) < t);
        }
        __syncthreads();
    }
    bool msk = !isinf(gt);
    if (rank < CAPn) d_slot[e * CAPn + rank] = msk ? t : -1;
    d_cof[e * Tn + t] = (rank < CAPn && msk) ? rank : -1;
}

__global__ void combine_kernel()
{
    int idx = blockIdx.x * blockDim.x + threadIdx.x;
    if (idx >= Tn * Dn) return;
    int t = idx / Dn, d = idx % Dn;
    float acc = 0.f, rho = 0.f;
#pragma unroll
    for (int e = 0; e < NEn; e++) {
        int c = d_cof[e * Tn + t];
        if (c >= 0) {
            float w = d_probs8[t * NEn + e];
            rho += w;
            acc += w * d_exout[((long long)e * CAPn + c) * Dn + d];
        }
    }
    float hv = d_h[idx];
    d_h[idx] = hv + acc - rho * hv;
}

// ---------------- host orchestration ----------------
static cudaStream_t g_s2 = nullptr;       // FFN branch
static cudaStream_t g_s3 = nullptr;       // attention second half
static cudaEvent_t  g_ev_fork = nullptr, g_ev_join2 = nullptr, g_ev_join3 = nullptr;

extern "C" void kernel_launch(void* const* d_in, const int* in_sizes, int n_in,
                              void* d_out, int out_size)
{
    (void)in_sizes; (void)n_in; (void)out_size;
    const int*   ids      = (const int*)d_in[0];
    const float* embed_w  = (const float*)d_in[1];
    const float* router_w = (const float*)d_in[2];
    const float* attn_qkv = (const float*)d_in[3];
    const float* attn_o   = (const float*)d_in[4];
    const float* attn_ln  = (const float*)d_in[5];
    const float* ffn_w1   = (const float*)d_in[6];
    const float* ffn_w2   = (const float*)d_in[7];
    const float* ffn_ln   = (const float*)d_in[8];
    const float* bb_qkv   = (const float*)d_in[9];
    const float* bb_o     = (const float*)d_in[10];
    const float* bb_ln    = (const float*)d_in[11];
    const float* lnout_s  = (const float*)d_in[12];
    float* out = (float*)d_out;

    if (!g_s2) {
        cudaStreamCreateWithFlags(&g_s2, cudaStreamNonBlocking);
        cudaStreamCreateWithFlags(&g_s3, cudaStreamNonBlocking);
        cudaEventCreateWithFlags(&g_ev_fork, cudaEventDisableTiming);
        cudaEventCreateWithFlags(&g_ev_join2, cudaEventDisableTiming);
        cudaEventCreateWithFlags(&g_ev_join3, cudaEventDisableTiming);
    }

    float *h, *u, *qkv, *att, *sc, *logits, *eu, *eqkv, *eatt, *ffh, *exout, *xin;
    int* slot;
    cudaGetSymbolAddress((void**)&h, d_h);
    cudaGetSymbolAddress((void**)&u, d_u);
    cudaGetSymbolAddress((void**)&qkv, d_qkv);
    cudaGetSymbolAddress((void**)&att, d_att);
    cudaGetSymbolAddress((void**)&sc, d_sc);
    cudaGetSymbolAddress((void**)&logits, d_logits);
    cudaGetSymbolAddress((void**)&eu, d_eu);
    cudaGetSymbolAddress((void**)&eqkv, d_eqkv);
    cudaGetSymbolAddress((void**)&eatt, d_eatt);
    cudaGetSymbolAddress((void**)&ffh, d_ffh);
    cudaGetSymbolAddress((void**)&exout, d_exout);
    cudaGetSymbolAddress((void**)&xin, d_xin);
    cudaGetSymbolAddress((void**)&slot, d_slot);

    auto NT = [](const float* A, const float* B, float* C, const float* R,
                 int M, int N, int K, int lda, int ldb, int ldc, int ldr,
                 long long sA, long long sB, long long sC, long long sR, int nb,
                 float alpha, int act, int causal, cudaStream_t st) {
        dim3 g(N / 64, M / 128, nb);
        gemm_tf32x3<true><<<g, 256, 0, st>>>(A, B, C, R, M, N, K, lda, ldb, ldc, ldr,
                                             sA, sB, sC, sR, alpha, act, causal, 0, 0, 0, 0);
    };
    auto NN = [](const float* A, const float* B, float* C,
                 int M, int N, int K, int lda, int ldb, int ldc,
                 long long sA, long long sB, long long sC, int nb, int causal,
                 cudaStream_t st) {
        dim3 g(N / 64, M / 128, nb);
        gemm_tf32x3<false><<<g, 256, 0, st>>>(A, B, C, nullptr, M, N, K, lda, ldb, ldc, 0,
                                              sA, sB, sC, 0, 1.f, 0, causal, 0, 0, 0, 0);
    };

    // ---- backbone ----
    embed_kernel<<<(Tn * Dn + 255) / 256, 256>>>(ids, embed_w);
    rope_table_kernel<<<Tn, 32>>>();
    rmsnorm_kernel<<<Tn, 256>>>(h, u, bb_ln);
    NT(u, bb_qkv, qkv, nullptr, Tn, 3 * Dn, Dn, Dn, Dn, 3 * Dn, 0, 0, 0, 0, 0, 1, 1.f, 0, 0, 0);
    rope_apply_kernel<<<dim3(Tn, 1), 256>>>(qkv, 0, nullptr, 0);

    // fork: heads 0-3 on stream 0, heads 4-7 on s3 (pipeline scores/softmax/AV)
    cudaEventRecord(g_ev_fork, 0);
    cudaStreamWaitEvent(g_s3, g_ev_fork, 0);
    for (int half = 0; half < 2; half++) {
        cudaStream_t st = half ? g_s3 : (cudaStream_t)0;
        const float* q0 = qkv + half * 4 * DHn;
        float* sc0 = sc + (long long)half * 4 * Tn * Tn;
        NT(q0, q0 + Dn, sc0, nullptr, Tn, Tn, DHn, 3 * Dn, 3 * Dn, Tn, 0,
           64, 64, (long long)Tn * Tn, 0, 4, 0.125f, 0, 1, st);
        softmax_causal<<<dim3(Tn, 4), 256, 0, st>>>(sc0, Tn);
        NN(sc0, qkv + 2 * Dn + half * 4 * DHn, att + half * 4 * DHn,
           Tn, DHn, Tn, Tn, 3 * Dn, Dn,
           (long long)Tn * Tn, 64, 64, 4, 1, st);
    }
    cudaEventRecord(g_ev_join3, g_s3);
    cudaStreamWaitEvent(0, g_ev_join3, 0);
    NT(att, bb_o, h, h, Tn, Dn, Dn, Dn, Dn, Dn, Dn, 0, 0, 0, 0, 1, 1.f, 0, 0, 0);

    // ---- hops ----
    for (int hop = 0; hop < 2; hop++) {
        {   // router logits (N=9): SIMT fp32 path
            dim3 g(1, (Tn + 63) / 64, 1);
            gemm_nt<<<g, 256>>>(h, router_w + hop * 9 * Dn, logits,
                                Tn, 9, Dn, Dn, Dn, 9);
        }
        router_post_kernel<<<(Tn + 255) / 256, 256>>>();
        rank_kernel<<<dim3(Tn / 256, NEn), 256>>>();
        gather_rmsnorm_kernel<<<dim3(CAPn, NEn), 256>>>(attn_ln, ffn_ln);

        // ---- fork: FFN on s2; attention half 1 on s3; half 0 on stream 0 ----
        cudaEventRecord(g_ev_fork, 0);
        cudaStreamWaitEvent(g_s2, g_ev_fork, 0);
        cudaStreamWaitEvent(g_s3, g_ev_fork, 0);

        // FFN experts on g_s2 (eu batches [4..8)), gelu fused into w1 GEMM
        NT(eu + 4LL * CAPn * Dn, ffn_w1, ffh, nullptr, CAPn, 4 * Dn, Dn, Dn, Dn, 4 * Dn, 0,
           (long long)CAPn * Dn, 4LL * Dn * Dn, (long long)CAPn * 4 * Dn, 0, 4, 1.f, 1, 0, g_s2);
        NT(ffh, ffn_w2, exout + CAPn * Dn, xin + CAPn * Dn, CAPn, Dn, 4 * Dn,
           4 * Dn, 4 * Dn, Dn, Dn,
           (long long)CAPn * 4 * Dn, 4LL * Dn * Dn, 2LL * CAPn * Dn, 2LL * CAPn * Dn, 4,
           1.f, 0, 0, g_s2);

        // attention halves: experts j={2k, 2k+1} pipelined across stream 0 / s3
        for (int k = 0; k < 2; k++) {
            cudaStream_t st = k ? g_s3 : (cudaStream_t)0;
            const float* euk  = eu + (long long)k * 2 * CAPn * Dn;
            const float* wq   = attn_qkv + (long long)k * 2 * (3LL * Dn * Dn);  // weights j=2k..
            const float* wo   = attn_o + (long long)k * 2 * ((long long)Dn * Dn);
            float* eqk  = eqkv + (long long)k * 2 * CAPn * 3 * Dn;
            float* sck  = sc + (long long)k * 16 * CAPn * CAPn;
            float* eak  = eatt + (long long)k * 2 * CAPn * Dn;
            float* exk  = exout + (long long)k * 2 * (2LL * CAPn * Dn);
            const float* xik = xin + (long long)k * 2 * (2LL * CAPn * Dn);
            NT(euk, wq, eqk, nullptr, CAPn, 3 * Dn, Dn, Dn, Dn, 3 * Dn, 0,
               (long long)CAPn * Dn, 3LL * Dn * Dn, (long long)CAPn * 3 * Dn, 0, 2,
               1.f, 0, 0, st);
            rope_apply_kernel<<<dim3(CAPn, 2), 256, 0, st>>>(eqk, (long long)CAPn * 3 * Dn,
                                                             slot + k * 2 * (2 * CAPn), 2 * CAPn);
            {   // scores: z = j*8 + head over 2 experts
                dim3 g(CAPn / 64, CAPn / 128, 16);
                gemm_tf32x3<true><<<g, 256, 0, st>>>(eqk, eqk + Dn, sck, nullptr,
                    CAPn, CAPn, DHn, 3 * Dn, 3 * Dn, CAPn, 0,
                    64, 64, (long long)CAPn * CAPn, 0, 0.125f, 0, 1,
                    1, 3LL * CAPn * Dn, 3LL * CAPn * Dn, 8LL * CAPn * CAPn);
            }
            softmax_causal<<<dim3(CAPn, 16), 256, 0, st>>>(sck, CAPn);
            {   // AV
                dim3 g(DHn / 64, CAPn / 128, 16);
                gemm_tf32x3<false><<<g, 256, 0, st>>>(sck, eqk + 2 * Dn, eak, nullptr,
                    CAPn, DHn, CAPn, CAPn, 3 * Dn, Dn, 0,
                    (long long)CAPn * CAPn, 64, 64, 0, 1.f, 0, 1,
                    1, 8LL * CAPn * CAPn, 3LL * CAPn * Dn, (long long)CAPn * Dn);
            }
            NT(eak, wo, exk, xik, CAPn, Dn, Dn, Dn, Dn, Dn, Dn,
               (long long)CAPn * Dn, (long long)Dn * Dn, 2LL * CAPn * Dn, 2LL * CAPn * Dn, 2,
               1.f, 0, 0, st);
        }

        // ---- join: stream 0 waits for FFN + attention half 1 ----
        cudaEventRecord(g_ev_join2, g_s2);
        cudaEventRecord(g_ev_join3, g_s3);
        cudaStreamWaitEvent(0, g_ev_join2, 0);
        cudaStreamWaitEvent(0, g_ev_join3, 0);

        combine_kernel<<<(Tn * Dn + 255) / 256, 256>>>();
    }

    // ---- final rmsnorm -> output ----
    rmsnorm_kernel<<<Tn, 256>>>(h, out, lnout_s);
}